// round 1
// baseline (speedup 1.0000x reference)
#include <cuda_runtime.h>
#include <cuda_bf16.h>
#include <math.h>

// Problem constants
#define BB 2
#define SS 2048
#define DD 1024
#define FF 4096
#define HH 16
#define DKK 64
#define MM (BB*SS)          // 4096

// ---------------- scratch (static device memory; no allocation APIs) ----------------
__device__ float g_xn   [MM*DD];        // 16 MB (reused for xn1 and xn2)
__device__ float g_q    [MM*DD];        // 16 MB, layout [M, D] (head h at cols h*64..)
__device__ float g_k    [MM*DD];
__device__ float g_v    [MM*DD];
__device__ float g_attn [MM*DD];        // attention output, [M, D]
__device__ float g_x1   [MM*DD];        // x + O-proj
__device__ float g_h    [MM*FF];        // 64 MB FFN hidden
__device__ float g_score[(long long)BB*HH*SS*SS]; // 1 GB scores/probs

// ---------------- reductions ----------------
__device__ __forceinline__ float warpSum(float v) {
#pragma unroll
    for (int o = 16; o > 0; o >>= 1) v += __shfl_xor_sync(0xffffffffu, v, o);
    return v;
}
__device__ __forceinline__ float warpMax(float v) {
#pragma unroll
    for (int o = 16; o > 0; o >>= 1) v = fmaxf(v, __shfl_xor_sync(0xffffffffu, v, o));
    return v;
}
__device__ float blockSum(float v) {
    __shared__ float sh[8];
    int lane = threadIdx.x & 31, w = threadIdx.x >> 5;
    v = warpSum(v);
    if (lane == 0) sh[w] = v;
    __syncthreads();
    if (w == 0) {
        float t = (lane < 8) ? sh[lane] : 0.0f;
        t = warpSum(t);
        if (lane == 0) sh[0] = t;
    }
    __syncthreads();
    float out = sh[0];
    __syncthreads();
    return out;
}
__device__ float blockMax(float v) {
    __shared__ float sh[8];
    int lane = threadIdx.x & 31, w = threadIdx.x >> 5;
    v = warpMax(v);
    if (lane == 0) sh[w] = v;
    __syncthreads();
    if (w == 0) {
        float t = (lane < 8) ? sh[lane] : -INFINITY;
        t = warpMax(t);
        if (lane == 0) sh[0] = t;
    }
    __syncthreads();
    float out = sh[0];
    __syncthreads();
    return out;
}

// ---------------- LayerNorm (torch-style: unbiased std, eps added to std) ----------------
__global__ void ln_kernel(const float* __restrict__ x, float* __restrict__ y,
                          const float* __restrict__ alpha, const float* __restrict__ beta) {
    long long row = blockIdx.x;
    const float* xr = x + row * DD;
    float* yr = y + row * DD;
    float v[4];
    float s = 0.0f;
#pragma unroll
    for (int r = 0; r < 4; r++) {
        v[r] = xr[threadIdx.x + r * 256];
        s += v[r];
    }
    float mean = blockSum(s) * (1.0f / DD);
    float s2 = 0.0f;
#pragma unroll
    for (int r = 0; r < 4; r++) {
        float d = v[r] - mean;
        s2 += d * d;
    }
    float var = blockSum(s2) * (1.0f / (DD - 1));
    float a = alpha[0], b = beta[0];
    float inv = a / (sqrtf(var) + 1e-6f);
#pragma unroll
    for (int r = 0; r < 4; r++)
        yr[threadIdx.x + r * 256] = (v[r] - mean) * inv + b;
}

// ---------------- generic tiled GEMM ----------------
// C[m,n] = sum_k A[m,k] * B'[n,k]   (BT=true : B is [N,K] row-major, "NT")
//        = sum_k A[m,k] * B [k,n]   (BT=false: B is [K,N] row-major, "NN")
// Batched over grid.z; per-batch offsets decomposed as z = outer*innerCnt + inner.
// Epilogue: optional bias[n], relu, residual (res has same [m,n] layout/ld as C, non-batched).
template<bool BT>
__global__ void __launch_bounds__(256)
gemm128(const float* __restrict__ A, const float* __restrict__ Bm,
        const float* __restrict__ bias, const float* __restrict__ res,
        float* __restrict__ C,
        int M, int N, int K, int lda, int ldb, int ldc,
        long long aOut, long long aIn, long long bOut, long long bIn,
        long long cOut, long long cIn, int innerCnt,
        int doBias, int doRelu, int doRes)
{
    const int BM = 128, BN = 128, BK = 16;
    __shared__ float As[BK][BM];
    __shared__ float Bs[BK][BN];

    int z = blockIdx.z;
    int zo = z / innerCnt, zi = z % innerCnt;
    A  += zo * aOut + zi * aIn;
    Bm += zo * bOut + zi * bIn;
    C  += zo * cOut + zi * cIn;

    int m0 = blockIdx.y * BM;
    int n0 = blockIdx.x * BN;
    int t = threadIdx.x;
    int tx = t & 15, ty = t >> 4;

    float acc[8][8];
#pragma unroll
    for (int i = 0; i < 8; i++)
#pragma unroll
        for (int j = 0; j < 8; j++) acc[i][j] = 0.0f;

    for (int k0 = 0; k0 < K; k0 += BK) {
        // ---- load A tile [BM][BK] -> As[k][m]
#pragma unroll
        for (int it = 0; it < 2; it++) {
            int s = t + it * 256;
            int row = s >> 2, kq = s & 3;
            float4 va = *(const float4*)(A + (long long)(m0 + row) * lda + k0 + kq * 4);
            As[kq * 4 + 0][row] = va.x;
            As[kq * 4 + 1][row] = va.y;
            As[kq * 4 + 2][row] = va.z;
            As[kq * 4 + 3][row] = va.w;
        }
        // ---- load B tile -> Bs[k][n]
        if (BT) {
#pragma unroll
            for (int it = 0; it < 2; it++) {
                int s = t + it * 256;
                int row = s >> 2, kq = s & 3;       // row = n index
                float4 vb;
                if (n0 + row < N)
                    vb = *(const float4*)(Bm + (long long)(n0 + row) * ldb + k0 + kq * 4);
                else
                    vb = make_float4(0.f, 0.f, 0.f, 0.f);
                Bs[kq * 4 + 0][row] = vb.x;
                Bs[kq * 4 + 1][row] = vb.y;
                Bs[kq * 4 + 2][row] = vb.z;
                Bs[kq * 4 + 3][row] = vb.w;
            }
        } else {
#pragma unroll
            for (int it = 0; it < 2; it++) {
                int s = t + it * 256;
                int kr = s >> 5, nq = s & 31;
                int n = n0 + nq * 4;
                float4 vb;
                if (n + 3 < N) {
                    vb = *(const float4*)(Bm + (long long)(k0 + kr) * ldb + n);
                } else {
                    const float* bp = Bm + (long long)(k0 + kr) * ldb;
                    vb.x = (n + 0 < N) ? bp[n + 0] : 0.f;
                    vb.y = (n + 1 < N) ? bp[n + 1] : 0.f;
                    vb.z = (n + 2 < N) ? bp[n + 2] : 0.f;
                    vb.w = (n + 3 < N) ? bp[n + 3] : 0.f;
                }
                *(float4*)&Bs[kr][nq * 4] = vb;
            }
        }
        __syncthreads();

        // ---- compute
#pragma unroll
        for (int k = 0; k < BK; k++) {
            float a[8], b[8];
            *(float4*)(a)     = *(const float4*)&As[k][ty * 8];
            *(float4*)(a + 4) = *(const float4*)&As[k][ty * 8 + 4];
            *(float4*)(b)     = *(const float4*)&Bs[k][tx * 8];
            *(float4*)(b + 4) = *(const float4*)&Bs[k][tx * 8 + 4];
#pragma unroll
            for (int i = 0; i < 8; i++)
#pragma unroll
                for (int j = 0; j < 8; j++)
                    acc[i][j] = fmaf(a[i], b[j], acc[i][j]);
        }
        __syncthreads();
    }

    // ---- epilogue
#pragma unroll
    for (int i = 0; i < 8; i++) {
        int m = m0 + ty * 8 + i;
#pragma unroll
        for (int j = 0; j < 8; j++) {
            int n = n0 + tx * 8 + j;
            if (n < N) {
                float vv = acc[i][j];
                if (doBias) vv += bias[n];
                if (doRelu) vv = fmaxf(vv, 0.0f);
                if (doRes)  vv += res[(long long)m * ldc + n];
                C[(long long)m * ldc + n] = vv;
            }
        }
    }
}

// ---------------- row softmax with mask ----------------
// One block per (b,h,q) row; row length S. mask is [B,S] ints (shape (B,1,1,S)).
__global__ void softmax_kernel(float* __restrict__ score, const int* __restrict__ mask) {
    long long row = blockIdx.x;                 // 0 .. B*H*S-1
    int b = (int)(row / ((long long)HH * SS));
    float* p = score + row * SS;
    const int* mrow = mask + (long long)b * SS;

    float vals[8];
    float lm = -INFINITY;
#pragma unroll
    for (int r = 0; r < 8; r++) {
        int k = threadIdx.x + r * 256;
        float v = p[k];
        if (mrow[k] == 0) v = -INFINITY;
        vals[r] = v;
        lm = fmaxf(lm, v);
    }
    float m = blockMax(lm);
    float ls = 0.0f;
#pragma unroll
    for (int r = 0; r < 8; r++) {
        float e = expf(vals[r] - m);
        vals[r] = e;
        ls += e;
    }
    float s = blockSum(ls);
    float inv = 1.0f / s;
#pragma unroll
    for (int r = 0; r < 8; r++) {
        int k = threadIdx.x + r * 256;
        p[k] = vals[r] * inv;
    }
}

// ---------------- host launch ----------------
extern "C" void kernel_launch(void* const* d_in, const int* in_sizes, int n_in,
                              void* d_out, int out_size) {
    const float* x      = (const float*)d_in[0];
    const int*   mask   = (const int*)  d_in[1];
    const float* wq     = (const float*)d_in[2];
    const float* bq     = (const float*)d_in[3];
    const float* wk     = (const float*)d_in[4];
    const float* bk     = (const float*)d_in[5];
    const float* wv     = (const float*)d_in[6];
    const float* bv     = (const float*)d_in[7];
    const float* wo     = (const float*)d_in[8];
    const float* bo     = (const float*)d_in[9];
    const float* w1     = (const float*)d_in[10];
    const float* b1     = (const float*)d_in[11];
    const float* w2     = (const float*)d_in[12];
    const float* b2     = (const float*)d_in[13];
    const float* alpha1 = (const float*)d_in[14];
    const float* beta1  = (const float*)d_in[15];
    const float* alpha2 = (const float*)d_in[16];
    const float* beta2  = (const float*)d_in[17];
    float* out = (float*)d_out;

    float *xn, *q, *k, *v, *attn, *x1, *h, *score;
    cudaGetSymbolAddress((void**)&xn,    g_xn);
    cudaGetSymbolAddress((void**)&q,     g_q);
    cudaGetSymbolAddress((void**)&k,     g_k);
    cudaGetSymbolAddress((void**)&v,     g_v);
    cudaGetSymbolAddress((void**)&attn,  g_attn);
    cudaGetSymbolAddress((void**)&x1,    g_x1);
    cudaGetSymbolAddress((void**)&h,     g_h);
    cudaGetSymbolAddress((void**)&score, g_score);

    const long long SD  = (long long)SS * DD;     // per-batch stride in q/k/v
    const long long S2  = (long long)SS * SS;     // per-head score stride
    const long long HS2 = (long long)HH * S2;     // per-batch score stride

    // 1) LN1
    ln_kernel<<<MM, 256>>>(x, xn, alpha1, beta1);

    // 2-4) Q/K/V projections: [4096,1024] = xn @ W^T + b    (NT)
    {
        dim3 g(DD / 128, MM / 128, 1);
        gemm128<true><<<g, 256>>>(xn, wq, bq, nullptr, q,
                                  MM, DD, DD, DD, DD, DD,
                                  0, 0, 0, 0, 0, 0, 1, 1, 0, 0);
        gemm128<true><<<g, 256>>>(xn, wk, bk, nullptr, k,
                                  MM, DD, DD, DD, DD, DD,
                                  0, 0, 0, 0, 0, 0, 1, 1, 0, 0);
        gemm128<true><<<g, 256>>>(xn, wv, bv, nullptr, v,
                                  MM, DD, DD, DD, DD, DD,
                                  0, 0, 0, 0, 0, 0, 1, 1, 0, 0);
    }

    // 5) scores: per (b,h): S[q,k] = Q @ K^T   (NT, batched over 32 heads)
    {
        dim3 g(SS / 128, SS / 128, BB * HH);
        gemm128<true><<<g, 256>>>(q, k, nullptr, nullptr, score,
                                  SS, SS, DKK, DD, DD, SS,
                                  SD, DKK, SD, DKK, HS2, S2, HH, 0, 0, 0);
    }

    // 6) softmax rows (with mask)
    softmax_kernel<<<BB * HH * SS, 256>>>(score, mask);

    // 7) attn = P @ V   (NN, batched; N = 64)
    {
        dim3 g(1, SS / 128, BB * HH);
        gemm128<false><<<g, 256>>>(score, v, nullptr, nullptr, attn,
                                   SS, DKK, SS, SS, DD, DD,
                                   HS2, S2, SD, DKK, SD, DKK, HH, 0, 0, 0);
    }

    // 8) x1 = x + attn @ wo^T + bo   (NT + bias + residual)
    {
        dim3 g(DD / 128, MM / 128, 1);
        gemm128<true><<<g, 256>>>(attn, wo, bo, x, x1,
                                  MM, DD, DD, DD, DD, DD,
                                  0, 0, 0, 0, 0, 0, 1, 1, 0, 1);
    }

    // 9) LN2 (reuse xn)
    ln_kernel<<<MM, 256>>>(x1, xn, alpha2, beta2);

    // 10) h = relu(xn @ w1^T + b1)   [4096,4096]
    {
        dim3 g(FF / 128, MM / 128, 1);
        gemm128<true><<<g, 256>>>(xn, w1, b1, nullptr, h,
                                  MM, FF, DD, DD, DD, FF,
                                  0, 0, 0, 0, 0, 0, 1, 1, 1, 0);
    }

    // 11) out = x1 + h @ w2^T + b2
    {
        dim3 g(DD / 128, MM / 128, 1);
        gemm128<true><<<g, 256>>>(h, w2, b2, x1, out,
                                  MM, DD, FF, FF, FF, DD,
                                  0, 0, 0, 0, 0, 0, 1, 1, 0, 1);
    }
}

// round 2
// speedup vs baseline: 2.1273x; 2.1273x over previous
#include <cuda_runtime.h>
#include <cuda_bf16.h>
#include <math.h>
#include <stdint.h>

// Problem constants
#define BB 2
#define SS 2048
#define DD 1024
#define FF 4096
#define HH 16
#define DKK 64
#define MM (BB*SS)          // 4096

// ---------------- scratch (static device memory; no allocation APIs) ----------------
__device__ float g_xn   [MM*DD];
__device__ float g_q    [MM*DD];
__device__ float g_k    [MM*DD];
__device__ float g_v    [MM*DD];
__device__ float g_attn [MM*DD];
__device__ float g_x1   [MM*DD];
__device__ float g_h    [MM*FF];
__device__ float g_score[(long long)BB*HH*SS*SS]; // 1 GB scores/probs

// ---------------- reductions ----------------
__device__ __forceinline__ float warpSum(float v) {
#pragma unroll
    for (int o = 16; o > 0; o >>= 1) v += __shfl_xor_sync(0xffffffffu, v, o);
    return v;
}
__device__ __forceinline__ float warpMax(float v) {
#pragma unroll
    for (int o = 16; o > 0; o >>= 1) v = fmaxf(v, __shfl_xor_sync(0xffffffffu, v, o));
    return v;
}
__device__ float blockSum(float v) {
    __shared__ float sh[8];
    int lane = threadIdx.x & 31, w = threadIdx.x >> 5;
    v = warpSum(v);
    if (lane == 0) sh[w] = v;
    __syncthreads();
    if (w == 0) {
        float t = (lane < 8) ? sh[lane] : 0.0f;
        t = warpSum(t);
        if (lane == 0) sh[0] = t;
    }
    __syncthreads();
    float out = sh[0];
    __syncthreads();
    return out;
}
__device__ float blockMax(float v) {
    __shared__ float sh[8];
    int lane = threadIdx.x & 31, w = threadIdx.x >> 5;
    v = warpMax(v);
    if (lane == 0) sh[w] = v;
    __syncthreads();
    if (w == 0) {
        float t = (lane < 8) ? sh[lane] : -INFINITY;
        t = warpMax(t);
        if (lane == 0) sh[0] = t;
    }
    __syncthreads();
    float out = sh[0];
    __syncthreads();
    return out;
}

// ---------------- LayerNorm (torch-style: unbiased std, eps added to std) ----------------
__global__ void ln_kernel(const float* __restrict__ x, float* __restrict__ y,
                          const float* __restrict__ alpha, const float* __restrict__ beta) {
    long long row = blockIdx.x;
    const float* xr = x + row * DD;
    float* yr = y + row * DD;
    float v[4];
    float s = 0.0f;
#pragma unroll
    for (int r = 0; r < 4; r++) {
        v[r] = xr[threadIdx.x + r * 256];
        s += v[r];
    }
    float mean = blockSum(s) * (1.0f / DD);
    float s2 = 0.0f;
#pragma unroll
    for (int r = 0; r < 4; r++) {
        float d = v[r] - mean;
        s2 += d * d;
    }
    float var = blockSum(s2) * (1.0f / (DD - 1));
    float a = alpha[0], b = beta[0];
    float inv = a / (sqrtf(var) + 1e-6f);
#pragma unroll
    for (int r = 0; r < 4; r++)
        yr[threadIdx.x + r * 256] = (v[r] - mean) * inv + b;
}

// ---------------- tf32 helpers ----------------
__device__ __forceinline__ uint32_t f2tf(float f) {
    uint32_t r;
    asm("cvt.rna.tf32.f32 %0, %1;" : "=r"(r) : "f"(f));
    return r;
}
__device__ __forceinline__ void mma_tf32(float* c,
                                         uint32_t a0, uint32_t a1, uint32_t a2, uint32_t a3,
                                         uint32_t b0, uint32_t b1) {
    asm volatile(
        "mma.sync.aligned.m16n8k8.row.col.f32.tf32.tf32.f32 "
        "{%0,%1,%2,%3},{%4,%5,%6,%7},{%8,%9},{%0,%1,%2,%3};"
        : "+f"(c[0]), "+f"(c[1]), "+f"(c[2]), "+f"(c[3])
        : "r"(a0), "r"(a1), "r"(a2), "r"(a3), "r"(b0), "r"(b1));
}

// ---------------- tensor-core GEMM ----------------
// C[m,n] = sum_k A[m,k]*B'[n,k]   (BT=true : B is [N,K] row-major)
//        = sum_k A[m,k]*B [k,n]   (BT=false: B is [K,N] row-major)
// BM=128 fixed; BN, warp microtiling templated. SPLIT=1 -> 3-mma split-tf32
// (fp32-quality accumulation). M % 128 == 0, N % BN == 0, K % 16 == 0 assumed.
template<int BN, int MT, int NT8, bool BT, int SPLIT>
__global__ void __launch_bounds__(256)
gemm_tc(const float* __restrict__ A, const float* __restrict__ Bm,
        const float* __restrict__ bias, const float* __restrict__ res,
        float* __restrict__ C,
        int M, int N, int K, int lda, int ldb, int ldc,
        long long aOut, long long aIn, long long bOut, long long bIn,
        long long cOut, long long cIn, int innerCnt,
        int doBias, int doRelu, int doRes)
{
    constexpr int BM = 128, BK = 16;
    constexpr int AST = BK + 4;                 // 20: conflict-free frag reads
    constexpr int BSTN = BN + 8;                // NN layout stride
    constexpr int WGN = BN / (NT8 * 8);         // warps along n
    constexpr int BS_SIZE = BT ? (BN * AST) : (BK * BSTN);

    __shared__ float As[BM * AST];
    __shared__ float Bs[BS_SIZE];

    int z = blockIdx.z;
    int zo = z / innerCnt, zi = z % innerCnt;
    A  += zo * aOut + zi * aIn;
    Bm += zo * bOut + zi * bIn;
    C  += zo * cOut + zi * cIn;

    const int m0 = blockIdx.y * BM;
    const int n0 = blockIdx.x * BN;
    const int t = threadIdx.x;
    const int lane = t & 31, w = t >> 5;
    const int gid = lane >> 2, tig = lane & 3;
    const int wn = w % WGN, wm = w / WGN;
    const int mBase = wm * MT * 16;
    const int nBase = wn * NT8 * 8;

    float acc[MT][NT8][4];
#pragma unroll
    for (int i = 0; i < MT; i++)
#pragma unroll
        for (int j = 0; j < NT8; j++)
#pragma unroll
            for (int r = 0; r < 4; r++) acc[i][j][r] = 0.0f;

    for (int k0 = 0; k0 < K; k0 += BK) {
        // ---- stage A tile [128 x 16]
#pragma unroll
        for (int it = 0; it < 2; it++) {
            int s = t + it * 256;
            int row = s >> 2, kq = s & 3;
            float4 va = *(const float4*)(A + (long long)(m0 + row) * lda + k0 + kq * 4);
            *(float4*)&As[row * AST + kq * 4] = va;
        }
        // ---- stage B tile
        if (BT) {
#pragma unroll
            for (int it = 0; it < 2; it++) {
                int s = t + it * 256;
                int row = s >> 2, kq = s & 3;       // row = n index
                float4 vb = *(const float4*)(Bm + (long long)(n0 + row) * ldb + k0 + kq * 4);
                *(float4*)&Bs[row * AST + kq * 4] = vb;
            }
        } else {
            // BN == 64: 16 x 64 tile, one float4/thread
            int kr = t >> 4, nq = t & 15;
            float4 vb = *(const float4*)(Bm + (long long)(k0 + kr) * ldb + n0 + nq * 4);
            *(float4*)&Bs[kr * BSTN + nq * 4] = vb;
        }
        __syncthreads();

#pragma unroll
        for (int kk = 0; kk < BK; kk += 8) {
            // ---- B fragments
            uint32_t bh[NT8][2], bl[NT8][2];
#pragma unroll
            for (int nt = 0; nt < NT8; nt++) {
                float f0, f1;
                int nn = nBase + nt * 8 + gid;
                if (BT) {
                    f0 = Bs[nn * AST + kk + tig];
                    f1 = Bs[nn * AST + kk + tig + 4];
                } else {
                    f0 = Bs[(kk + tig) * BSTN + nn];
                    f1 = Bs[(kk + tig + 4) * BSTN + nn];
                }
                bh[nt][0] = f2tf(f0);
                bh[nt][1] = f2tf(f1);
                if (SPLIT) {
                    bl[nt][0] = f2tf(f0 - __uint_as_float(bh[nt][0]));
                    bl[nt][1] = f2tf(f1 - __uint_as_float(bh[nt][1]));
                }
            }
            // ---- A fragments + mma
#pragma unroll
            for (int mt = 0; mt < MT; mt++) {
                int r0 = mBase + mt * 16 + gid;
                float fa0 = As[r0 * AST + kk + tig];
                float fa1 = As[(r0 + 8) * AST + kk + tig];
                float fa2 = As[r0 * AST + kk + tig + 4];
                float fa3 = As[(r0 + 8) * AST + kk + tig + 4];
                uint32_t ah0 = f2tf(fa0), ah1 = f2tf(fa1), ah2 = f2tf(fa2), ah3 = f2tf(fa3);
                uint32_t al0, al1, al2, al3;
                if (SPLIT) {
                    al0 = f2tf(fa0 - __uint_as_float(ah0));
                    al1 = f2tf(fa1 - __uint_as_float(ah1));
                    al2 = f2tf(fa2 - __uint_as_float(ah2));
                    al3 = f2tf(fa3 - __uint_as_float(ah3));
                }
#pragma unroll
                for (int nt = 0; nt < NT8; nt++) {
                    mma_tf32(acc[mt][nt], ah0, ah1, ah2, ah3, bh[nt][0], bh[nt][1]);
                    if (SPLIT) {
                        mma_tf32(acc[mt][nt], ah0, ah1, ah2, ah3, bl[nt][0], bl[nt][1]);
                        mma_tf32(acc[mt][nt], al0, al1, al2, al3, bh[nt][0], bh[nt][1]);
                    }
                }
            }
        }
        __syncthreads();
    }

    // ---- epilogue
#pragma unroll
    for (int mt = 0; mt < MT; mt++) {
#pragma unroll
        for (int nt = 0; nt < NT8; nt++) {
            int row = m0 + mBase + mt * 16 + gid;
            int col = n0 + nBase + nt * 8 + tig * 2;
            float b0 = 0.f, b1 = 0.f;
            if (doBias) { b0 = bias[col]; b1 = bias[col + 1]; }
#pragma unroll
            for (int half = 0; half < 2; half++) {
                int r = row + half * 8;
                float v0 = acc[mt][nt][half * 2 + 0] + b0;
                float v1 = acc[mt][nt][half * 2 + 1] + b1;
                if (doRelu) { v0 = fmaxf(v0, 0.f); v1 = fmaxf(v1, 0.f); }
                if (doRes) {
                    float2 rr = *(const float2*)(res + (long long)r * ldc + col);
                    v0 += rr.x; v1 += rr.y;
                }
                *(float2*)(C + (long long)r * ldc + col) = make_float2(v0, v1);
            }
        }
    }
}

// ---------------- row softmax with mask ----------------
__global__ void softmax_kernel(float* __restrict__ score, const int* __restrict__ mask) {
    long long row = blockIdx.x;                 // 0 .. B*H*S-1
    int b = (int)(row / ((long long)HH * SS));
    float* p = score + row * SS;
    const int* mrow = mask + (long long)b * SS;

    float vals[8];
    float lm = -INFINITY;
#pragma unroll
    for (int r = 0; r < 8; r++) {
        int k = threadIdx.x + r * 256;
        float v = p[k];
        if (mrow[k] == 0) v = -INFINITY;
        vals[r] = v;
        lm = fmaxf(lm, v);
    }
    float m = blockMax(lm);
    float ls = 0.0f;
#pragma unroll
    for (int r = 0; r < 8; r++) {
        float e = expf(vals[r] - m);
        vals[r] = e;
        ls += e;
    }
    float s = blockSum(ls);
    float inv = 1.0f / s;
#pragma unroll
    for (int r = 0; r < 8; r++) {
        int k = threadIdx.x + r * 256;
        p[k] = vals[r] * inv;
    }
}

// ---------------- host launch ----------------
extern "C" void kernel_launch(void* const* d_in, const int* in_sizes, int n_in,
                              void* d_out, int out_size) {
    const float* x      = (const float*)d_in[0];
    const int*   mask   = (const int*)  d_in[1];
    const float* wq     = (const float*)d_in[2];
    const float* bq     = (const float*)d_in[3];
    const float* wk     = (const float*)d_in[4];
    const float* bk     = (const float*)d_in[5];
    const float* wv     = (const float*)d_in[6];
    const float* bv     = (const float*)d_in[7];
    const float* wo     = (const float*)d_in[8];
    const float* bo     = (const float*)d_in[9];
    const float* w1     = (const float*)d_in[10];
    const float* b1     = (const float*)d_in[11];
    const float* w2     = (const float*)d_in[12];
    const float* b2     = (const float*)d_in[13];
    const float* alpha1 = (const float*)d_in[14];
    const float* beta1  = (const float*)d_in[15];
    const float* alpha2 = (const float*)d_in[16];
    const float* beta2  = (const float*)d_in[17];
    float* out = (float*)d_out;

    float *xn, *q, *k, *v, *attn, *x1, *h, *score;
    cudaGetSymbolAddress((void**)&xn,    g_xn);
    cudaGetSymbolAddress((void**)&q,     g_q);
    cudaGetSymbolAddress((void**)&k,     g_k);
    cudaGetSymbolAddress((void**)&v,     g_v);
    cudaGetSymbolAddress((void**)&attn,  g_attn);
    cudaGetSymbolAddress((void**)&x1,    g_x1);
    cudaGetSymbolAddress((void**)&h,     g_h);
    cudaGetSymbolAddress((void**)&score, g_score);

    const long long SD  = (long long)SS * DD;     // per-batch stride in q/k/v
    const long long S2  = (long long)SS * SS;     // per-head score stride
    const long long HS2 = (long long)HH * S2;     // per-batch score stride

    // 1) LN1
    ln_kernel<<<MM, 256>>>(x, xn, alpha1, beta1);

    // 2-4) Q/K/V projections (NT). q,k use split-tf32 (feed exp); v plain tf32.
    {
        dim3 g(DD / 128, MM / 128, 1);
        gemm_tc<128,4,4,true,1><<<g, 256>>>(xn, wq, bq, nullptr, q,
                                  MM, DD, DD, DD, DD, DD,
                                  0, 0, 0, 0, 0, 0, 1, 1, 0, 0);
        gemm_tc<128,4,4,true,1><<<g, 256>>>(xn, wk, bk, nullptr, k,
                                  MM, DD, DD, DD, DD, DD,
                                  0, 0, 0, 0, 0, 0, 1, 1, 0, 0);
        gemm_tc<128,4,4,true,0><<<g, 256>>>(xn, wv, bv, nullptr, v,
                                  MM, DD, DD, DD, DD, DD,
                                  0, 0, 0, 0, 0, 0, 1, 1, 0, 0);
    }

    // 5) scores = Q @ K^T per head (NT, batched, split-tf32)
    {
        dim3 g(SS / 128, SS / 128, BB * HH);
        gemm_tc<128,4,4,true,1><<<g, 256>>>(q, k, nullptr, nullptr, score,
                                  SS, SS, DKK, DD, DD, SS,
                                  SD, DKK, SD, DKK, HS2, S2, HH, 0, 0, 0);
    }

    // 6) softmax rows (with mask)
    softmax_kernel<<<BB * HH * SS, 256>>>(score, mask);

    // 7) attn = P @ V (NN, batched; N=64; plain tf32)
    {
        dim3 g(1, SS / 128, BB * HH);
        gemm_tc<64,2,4,false,0><<<g, 256>>>(score, v, nullptr, nullptr, attn,
                                   SS, DKK, SS, SS, DD, DD,
                                   HS2, S2, SD, DKK, SD, DKK, HH, 0, 0, 0);
    }

    // 8) x1 = x + attn @ wo^T + bo
    {
        dim3 g(DD / 128, MM / 128, 1);
        gemm_tc<128,4,4,true,0><<<g, 256>>>(attn, wo, bo, x, x1,
                                  MM, DD, DD, DD, DD, DD,
                                  0, 0, 0, 0, 0, 0, 1, 1, 0, 1);
    }

    // 9) LN2 (reuse xn)
    ln_kernel<<<MM, 256>>>(x1, xn, alpha2, beta2);

    // 10) h = relu(xn @ w1^T + b1)
    {
        dim3 g(FF / 128, MM / 128, 1);
        gemm_tc<128,4,4,true,0><<<g, 256>>>(xn, w1, b1, nullptr, h,
                                  MM, FF, DD, DD, DD, FF,
                                  0, 0, 0, 0, 0, 0, 1, 1, 1, 0);
    }

    // 11) out = x1 + h @ w2^T + b2
    {
        dim3 g(DD / 128, MM / 128, 1);
        gemm_tc<128,4,4,true,0><<<g, 256>>>(h, w2, b2, x1, out,
                                  MM, DD, FF, FF, FF, DD,
                                  0, 0, 0, 0, 0, 0, 1, 1, 0, 1);
    }
}

// round 3
// speedup vs baseline: 2.4768x; 1.1643x over previous
#include <cuda_runtime.h>
#include <cuda_bf16.h>
#include <math.h>
#include <stdint.h>

// Problem constants
#define BB 2
#define SS 2048
#define DD 1024
#define FF 4096
#define HH 16
#define DKK 64
#define MM (BB*SS)          // 4096

// ---------------- scratch (static device memory; no allocation APIs) ----------------
__device__ float g_xn   [MM*DD];
__device__ float g_q    [MM*DD];
__device__ float g_k    [MM*DD];
__device__ float g_v    [MM*DD];
__device__ float g_attn [MM*DD];
__device__ float g_x1   [MM*DD];
__device__ float g_h    [MM*FF];

// ---------------- reductions ----------------
__device__ __forceinline__ float warpSum(float v) {
#pragma unroll
    for (int o = 16; o > 0; o >>= 1) v += __shfl_xor_sync(0xffffffffu, v, o);
    return v;
}
__device__ float blockSum(float v) {
    __shared__ float sh[8];
    int lane = threadIdx.x & 31, w = threadIdx.x >> 5;
    v = warpSum(v);
    if (lane == 0) sh[w] = v;
    __syncthreads();
    if (w == 0) {
        float t = (lane < 8) ? sh[lane] : 0.0f;
        t = warpSum(t);
        if (lane == 0) sh[0] = t;
    }
    __syncthreads();
    float out = sh[0];
    __syncthreads();
    return out;
}

// ---------------- LayerNorm (torch-style: unbiased std, eps added to std) ----------------
__global__ void ln_kernel(const float* __restrict__ x, float* __restrict__ y,
                          const float* __restrict__ alpha, const float* __restrict__ beta) {
    long long row = blockIdx.x;
    const float* xr = x + row * DD;
    float* yr = y + row * DD;
    float v[4];
    float s = 0.0f;
#pragma unroll
    for (int r = 0; r < 4; r++) {
        v[r] = xr[threadIdx.x + r * 256];
        s += v[r];
    }
    float mean = blockSum(s) * (1.0f / DD);
    float s2 = 0.0f;
#pragma unroll
    for (int r = 0; r < 4; r++) {
        float d = v[r] - mean;
        s2 += d * d;
    }
    float var = blockSum(s2) * (1.0f / (DD - 1));
    float a = alpha[0], b = beta[0];
    float inv = a / (sqrtf(var) + 1e-6f);
#pragma unroll
    for (int r = 0; r < 4; r++)
        yr[threadIdx.x + r * 256] = (v[r] - mean) * inv + b;
}

// ---------------- tf32 helpers ----------------
__device__ __forceinline__ uint32_t f2tf(float f) {
    uint32_t r;
    asm("cvt.rna.tf32.f32 %0, %1;" : "=r"(r) : "f"(f));
    return r;
}
__device__ __forceinline__ void mma_tf32(float* c,
                                         uint32_t a0, uint32_t a1, uint32_t a2, uint32_t a3,
                                         uint32_t b0, uint32_t b1) {
    asm volatile(
        "mma.sync.aligned.m16n8k8.row.col.f32.tf32.tf32.f32 "
        "{%0,%1,%2,%3},{%4,%5,%6,%7},{%8,%9},{%0,%1,%2,%3};"
        : "+f"(c[0]), "+f"(c[1]), "+f"(c[2]), "+f"(c[3])
        : "r"(a0), "r"(a1), "r"(a2), "r"(a3), "r"(b0), "r"(b1));
}

// ---------------- dense NT GEMM, tf32 staged in smem ----------------
// C[m,n] = sum_k A[m,k] * B[n,k] (+bias, relu, residual). M%128==0, N%128==0, K%16==0.
// SPLIT=1: hi/lo split-tf32 (fp32-quality), 3 mma per step.
template<int SPLIT>
__global__ void __launch_bounds__(256)
gemm_nt(const float* __restrict__ A, const float* __restrict__ Bm,
        const float* __restrict__ bias, const float* __restrict__ res,
        float* __restrict__ C,
        int M, int N, int K, int lda, int ldb, int ldc,
        int doBias, int doRelu, int doRes)
{
    constexpr int BK = 16;
    constexpr int AST = 20;
    __shared__ uint32_t Ah[128 * AST];
    __shared__ uint32_t Bh[128 * AST];
    __shared__ uint32_t Al[SPLIT ? 128 * AST : 1];
    __shared__ uint32_t Bl[SPLIT ? 128 * AST : 1];

    const int m0 = blockIdx.y * 128;
    const int n0 = blockIdx.x * 128;
    const int t = threadIdx.x;
    const int lane = t & 31, w = t >> 5;
    const int gid = lane >> 2, tig = lane & 3;
    const int wn = w & 3, wm = w >> 2;          // 4 warps n, 2 warps m
    const int mBase = wm * 64;                  // MT=4 (4 x m16)
    const int nBase = wn * 32;                  // NT8=4 (4 x n8)

    float acc[4][4][4];
#pragma unroll
    for (int i = 0; i < 4; i++)
#pragma unroll
        for (int j = 0; j < 4; j++)
#pragma unroll
            for (int r = 0; r < 4; r++) acc[i][j][r] = 0.0f;

    for (int k0 = 0; k0 < K; k0 += BK) {
#pragma unroll
        for (int it = 0; it < 2; it++) {
            int s = t + it * 256;
            int row = s >> 2, kq = (s & 3) * 4;
            float4 va = *(const float4*)(A + (long long)(m0 + row) * lda + k0 + kq);
            uint4 hi, lo;
            hi.x = f2tf(va.x); hi.y = f2tf(va.y); hi.z = f2tf(va.z); hi.w = f2tf(va.w);
            *(uint4*)&Ah[row * AST + kq] = hi;
            if (SPLIT) {
                lo.x = f2tf(va.x - __uint_as_float(hi.x));
                lo.y = f2tf(va.y - __uint_as_float(hi.y));
                lo.z = f2tf(va.z - __uint_as_float(hi.z));
                lo.w = f2tf(va.w - __uint_as_float(hi.w));
                *(uint4*)&Al[row * AST + kq] = lo;
            }
            float4 vb = *(const float4*)(Bm + (long long)(n0 + row) * ldb + k0 + kq);
            hi.x = f2tf(vb.x); hi.y = f2tf(vb.y); hi.z = f2tf(vb.z); hi.w = f2tf(vb.w);
            *(uint4*)&Bh[row * AST + kq] = hi;
            if (SPLIT) {
                lo.x = f2tf(vb.x - __uint_as_float(hi.x));
                lo.y = f2tf(vb.y - __uint_as_float(hi.y));
                lo.z = f2tf(vb.z - __uint_as_float(hi.z));
                lo.w = f2tf(vb.w - __uint_as_float(hi.w));
                *(uint4*)&Bl[row * AST + kq] = lo;
            }
        }
        __syncthreads();

#pragma unroll
        for (int kk = 0; kk < BK; kk += 8) {
            uint32_t bhf[4][2], blf[4][2];
#pragma unroll
            for (int nt = 0; nt < 4; nt++) {
                int nn = nBase + nt * 8 + gid;
                bhf[nt][0] = Bh[nn * AST + kk + tig];
                bhf[nt][1] = Bh[nn * AST + kk + tig + 4];
                if (SPLIT) {
                    blf[nt][0] = Bl[nn * AST + kk + tig];
                    blf[nt][1] = Bl[nn * AST + kk + tig + 4];
                }
            }
#pragma unroll
            for (int mt = 0; mt < 4; mt++) {
                int r0 = mBase + mt * 16 + gid;
                uint32_t ah0 = Ah[r0 * AST + kk + tig];
                uint32_t ah1 = Ah[(r0 + 8) * AST + kk + tig];
                uint32_t ah2 = Ah[r0 * AST + kk + tig + 4];
                uint32_t ah3 = Ah[(r0 + 8) * AST + kk + tig + 4];
                uint32_t al0, al1, al2, al3;
                if (SPLIT) {
                    al0 = Al[r0 * AST + kk + tig];
                    al1 = Al[(r0 + 8) * AST + kk + tig];
                    al2 = Al[r0 * AST + kk + tig + 4];
                    al3 = Al[(r0 + 8) * AST + kk + tig + 4];
                }
#pragma unroll
                for (int nt = 0; nt < 4; nt++) {
                    mma_tf32(acc[mt][nt], ah0, ah1, ah2, ah3, bhf[nt][0], bhf[nt][1]);
                    if (SPLIT) {
                        mma_tf32(acc[mt][nt], ah0, ah1, ah2, ah3, blf[nt][0], blf[nt][1]);
                        mma_tf32(acc[mt][nt], al0, al1, al2, al3, bhf[nt][0], bhf[nt][1]);
                    }
                }
            }
        }
        __syncthreads();
    }

#pragma unroll
    for (int mt = 0; mt < 4; mt++) {
#pragma unroll
        for (int nt = 0; nt < 4; nt++) {
            int row = m0 + mBase + mt * 16 + gid;
            int col = n0 + nBase + nt * 8 + tig * 2;
            float b0 = 0.f, b1 = 0.f;
            if (doBias) { b0 = bias[col]; b1 = bias[col + 1]; }
#pragma unroll
            for (int half = 0; half < 2; half++) {
                int r = row + half * 8;
                float v0 = acc[mt][nt][half * 2 + 0] + b0;
                float v1 = acc[mt][nt][half * 2 + 1] + b1;
                if (doRelu) { v0 = fmaxf(v0, 0.f); v1 = fmaxf(v1, 0.f); }
                if (doRes) {
                    float2 rr = *(const float2*)(res + (long long)r * ldc + col);
                    v0 += rr.x; v1 += rr.y;
                }
                *(float2*)(C + (long long)r * ldc + col) = make_float2(v0, v1);
            }
        }
    }
}

// ---------------- flash attention ----------------
// Grid (S/128, B*H). 256 threads = 8 warps; warp w owns q-rows [w*16, w*16+16).
// Per key-block of 128: QK^T (split-tf32), masked online softmax, P@V (tf32).
#define KSTR 68
#define VSTR 72
#define PSTR 140
#define FLASH_SMEM (4 * (2 * 128 * KSTR + 128 * VSTR + 128 * PSTR) + 512)

__global__ void __launch_bounds__(256, 1)
flash_kernel(const float* __restrict__ Q, const float* __restrict__ K,
             const float* __restrict__ V, const int* __restrict__ mask,
             float* __restrict__ O)
{
    extern __shared__ char smem_raw[];
    uint32_t* Khi = (uint32_t*)smem_raw;
    uint32_t* Klo = Khi + 128 * KSTR;
    uint32_t* Vs  = Klo + 128 * KSTR;
    uint32_t* Ps  = Vs + 128 * VSTR;
    float*    Qs  = (float*)Ps;                 // reused before first P store
    int*      Ms  = (int*)(Ps + 128 * PSTR);

    const int bh = blockIdx.y;
    const int b = bh >> 4, h = bh & 15;
    const int q0 = blockIdx.x * 128;
    const int t = threadIdx.x, lane = t & 31, w = t >> 5;
    const int gid = lane >> 2, tig = lane & 3;

    const float* Qbase = Q + ((long long)(b * SS + q0)) * DD + h * DKK;
    const float* Kbase = K + ((long long)b * SS) * DD + h * DKK;
    const float* Vbase = V + ((long long)b * SS) * DD + h * DKK;

    // ---- stage Q (fp32) then build per-warp register fragments (hi/lo)
    for (int i = t; i < 2048; i += 256) {
        int r = i >> 4, c = (i & 15) * 4;
        float4 vq = *(const float4*)(Qbase + (long long)r * DD + c);
        *(float4*)&Qs[r * KSTR + c] = vq;
    }
    __syncthreads();

    uint32_t qhi[8][4], qlo[8][4];
    {
        int r0 = w * 16 + gid;
#pragma unroll
        for (int ks = 0; ks < 8; ks++) {
            int c0 = ks * 8 + tig;
            float f0 = Qs[r0 * KSTR + c0];
            float f1 = Qs[(r0 + 8) * KSTR + c0];
            float f2 = Qs[r0 * KSTR + c0 + 4];
            float f3 = Qs[(r0 + 8) * KSTR + c0 + 4];
            qhi[ks][0] = f2tf(f0); qlo[ks][0] = f2tf(f0 - __uint_as_float(qhi[ks][0]));
            qhi[ks][1] = f2tf(f1); qlo[ks][1] = f2tf(f1 - __uint_as_float(qhi[ks][1]));
            qhi[ks][2] = f2tf(f2); qlo[ks][2] = f2tf(f2 - __uint_as_float(qhi[ks][2]));
            qhi[ks][3] = f2tf(f3); qlo[ks][3] = f2tf(f3 - __uint_as_float(qhi[ks][3]));
        }
    }

    float acc[8][4];
#pragma unroll
    for (int i = 0; i < 8; i++)
#pragma unroll
        for (int r = 0; r < 4; r++) acc[i][r] = 0.0f;
    float mrow0 = -1e30f, mrow1 = -1e30f;
    float lrow0 = 0.0f, lrow1 = 0.0f;

    for (int k0 = 0; k0 < SS; k0 += 128) {
        __syncthreads();   // prior iter's reads of Khi/Vs done
        // ---- stage K (hi/lo tf32) and V (tf32)
        for (int i = t; i < 2048; i += 256) {
            int r = i >> 4, c = (i & 15) * 4;
            float4 kv = *(const float4*)(Kbase + (long long)(k0 + r) * DD + c);
            uint4 hi, lo;
            hi.x = f2tf(kv.x); lo.x = f2tf(kv.x - __uint_as_float(hi.x));
            hi.y = f2tf(kv.y); lo.y = f2tf(kv.y - __uint_as_float(hi.y));
            hi.z = f2tf(kv.z); lo.z = f2tf(kv.z - __uint_as_float(hi.z));
            hi.w = f2tf(kv.w); lo.w = f2tf(kv.w - __uint_as_float(hi.w));
            *(uint4*)&Khi[r * KSTR + c] = hi;
            *(uint4*)&Klo[r * KSTR + c] = lo;
            float4 vv = *(const float4*)(Vbase + (long long)(k0 + r) * DD + c);
            uint4 vt;
            vt.x = f2tf(vv.x); vt.y = f2tf(vv.y); vt.z = f2tf(vv.z); vt.w = f2tf(vv.w);
            *(uint4*)&Vs[r * VSTR + c] = vt;
        }
        if (t < 128) Ms[t] = mask[(long long)b * SS + k0 + t];
        __syncthreads();

        // ---- QK^T: s[16][4] covers 16 q-rows x 128 keys for this warp
        float s[16][4];
#pragma unroll
        for (int nt = 0; nt < 16; nt++) {
            s[nt][0] = 0.f; s[nt][1] = 0.f; s[nt][2] = 0.f; s[nt][3] = 0.f;
        }
#pragma unroll
        for (int nt = 0; nt < 16; nt++) {
            int nrow = (nt * 8 + gid) * KSTR;
#pragma unroll
            for (int ks = 0; ks < 8; ks++) {
                int a = nrow + ks * 8 + tig;
                uint32_t kh0 = Khi[a], kh1 = Khi[a + 4];
                uint32_t kl0 = Klo[a], kl1 = Klo[a + 4];
                mma_tf32(s[nt], qhi[ks][0], qhi[ks][1], qhi[ks][2], qhi[ks][3], kh0, kh1);
                mma_tf32(s[nt], qhi[ks][0], qhi[ks][1], qhi[ks][2], qhi[ks][3], kl0, kl1);
                mma_tf32(s[nt], qlo[ks][0], qlo[ks][1], qlo[ks][2], qlo[ks][3], kh0, kh1);
            }
        }

        // ---- mask
#pragma unroll
        for (int nt = 0; nt < 16; nt++) {
            int c = nt * 8 + 2 * tig;
            if (Ms[c] == 0)     { s[nt][0] = -1e30f; s[nt][2] = -1e30f; }
            if (Ms[c + 1] == 0) { s[nt][1] = -1e30f; s[nt][3] = -1e30f; }
        }

        // ---- online softmax (rows gid and gid+8 of warp band)
        float tm0 = -1e30f, tm1 = -1e30f;
#pragma unroll
        for (int nt = 0; nt < 16; nt++) {
            tm0 = fmaxf(tm0, fmaxf(s[nt][0], s[nt][1]));
            tm1 = fmaxf(tm1, fmaxf(s[nt][2], s[nt][3]));
        }
        tm0 = fmaxf(tm0, __shfl_xor_sync(0xffffffffu, tm0, 1));
        tm0 = fmaxf(tm0, __shfl_xor_sync(0xffffffffu, tm0, 2));
        tm1 = fmaxf(tm1, __shfl_xor_sync(0xffffffffu, tm1, 1));
        tm1 = fmaxf(tm1, __shfl_xor_sync(0xffffffffu, tm1, 2));
        float mn0 = fmaxf(mrow0, tm0), mn1 = fmaxf(mrow1, tm1);
        float sc0 = __expf(mrow0 - mn0), sc1 = __expf(mrow1 - mn1);
        mrow0 = mn0; mrow1 = mn1;
        float rs0 = 0.f, rs1 = 0.f;
#pragma unroll
        for (int nt = 0; nt < 16; nt++) {
            s[nt][0] = __expf(s[nt][0] - mn0);
            s[nt][1] = __expf(s[nt][1] - mn0);
            s[nt][2] = __expf(s[nt][2] - mn1);
            s[nt][3] = __expf(s[nt][3] - mn1);
            rs0 += s[nt][0] + s[nt][1];
            rs1 += s[nt][2] + s[nt][3];
        }
        rs0 += __shfl_xor_sync(0xffffffffu, rs0, 1);
        rs0 += __shfl_xor_sync(0xffffffffu, rs0, 2);
        rs1 += __shfl_xor_sync(0xffffffffu, rs1, 1);
        rs1 += __shfl_xor_sync(0xffffffffu, rs1, 2);
        lrow0 = lrow0 * sc0 + rs0;
        lrow1 = lrow1 * sc1 + rs1;
#pragma unroll
        for (int nt = 0; nt < 8; nt++) {
            acc[nt][0] *= sc0; acc[nt][1] *= sc0;
            acc[nt][2] *= sc1; acc[nt][3] *= sc1;
        }

        // ---- store P (tf32) to warp-private rows of Ps
        {
            int r0 = (w * 16 + gid) * PSTR;
            int r1 = (w * 16 + gid + 8) * PSTR;
#pragma unroll
            for (int nt = 0; nt < 16; nt++) {
                int c = nt * 8 + 2 * tig;
                uint2 p0, p1;
                p0.x = f2tf(s[nt][0]); p0.y = f2tf(s[nt][1]);
                p1.x = f2tf(s[nt][2]); p1.y = f2tf(s[nt][3]);
                *(uint2*)&Ps[r0 + c] = p0;
                *(uint2*)&Ps[r1 + c] = p1;
            }
        }
        __syncwarp();

        // ---- P @ V -> acc
        {
            int pr0 = (w * 16 + gid) * PSTR;
            int pr1 = (w * 16 + gid + 8) * PSTR;
#pragma unroll
            for (int ks = 0; ks < 16; ks++) {
                int kk = ks * 8;
                uint32_t a0 = Ps[pr0 + kk + tig];
                uint32_t a1 = Ps[pr1 + kk + tig];
                uint32_t a2 = Ps[pr0 + kk + tig + 4];
                uint32_t a3 = Ps[pr1 + kk + tig + 4];
#pragma unroll
                for (int nt = 0; nt < 8; nt++) {
                    uint32_t b0 = Vs[(kk + tig) * VSTR + nt * 8 + gid];
                    uint32_t b1 = Vs[(kk + tig + 4) * VSTR + nt * 8 + gid];
                    mma_tf32(acc[nt], a0, a1, a2, a3, b0, b1);
                }
            }
        }
    }

    // ---- epilogue: normalize and write O[(b*S + q), h*64 + c]
    float inv0 = 1.0f / lrow0, inv1 = 1.0f / lrow1;
    long long rowg = (long long)(b * SS + q0 + w * 16 + gid);
#pragma unroll
    for (int nt = 0; nt < 8; nt++) {
        int col = h * DKK + nt * 8 + 2 * tig;
        *(float2*)(O + rowg * DD + col) =
            make_float2(acc[nt][0] * inv0, acc[nt][1] * inv0);
        *(float2*)(O + (rowg + 8) * DD + col) =
            make_float2(acc[nt][2] * inv1, acc[nt][3] * inv1);
    }
}

// ---------------- host launch ----------------
extern "C" void kernel_launch(void* const* d_in, const int* in_sizes, int n_in,
                              void* d_out, int out_size) {
    const float* x      = (const float*)d_in[0];
    const int*   mask   = (const int*)  d_in[1];
    const float* wq     = (const float*)d_in[2];
    const float* bq     = (const float*)d_in[3];
    const float* wk     = (const float*)d_in[4];
    const float* bk     = (const float*)d_in[5];
    const float* wv     = (const float*)d_in[6];
    const float* bv     = (const float*)d_in[7];
    const float* wo     = (const float*)d_in[8];
    const float* bo     = (const float*)d_in[9];
    const float* w1     = (const float*)d_in[10];
    const float* b1     = (const float*)d_in[11];
    const float* w2     = (const float*)d_in[12];
    const float* b2     = (const float*)d_in[13];
    const float* alpha1 = (const float*)d_in[14];
    const float* beta1  = (const float*)d_in[15];
    const float* alpha2 = (const float*)d_in[16];
    const float* beta2  = (const float*)d_in[17];
    float* out = (float*)d_out;

    float *xn, *q, *k, *v, *attn, *x1, *h;
    cudaGetSymbolAddress((void**)&xn,   g_xn);
    cudaGetSymbolAddress((void**)&q,    g_q);
    cudaGetSymbolAddress((void**)&k,    g_k);
    cudaGetSymbolAddress((void**)&v,    g_v);
    cudaGetSymbolAddress((void**)&attn, g_attn);
    cudaGetSymbolAddress((void**)&x1,   g_x1);
    cudaGetSymbolAddress((void**)&h,    g_h);

    cudaFuncSetAttribute(flash_kernel, cudaFuncAttributeMaxDynamicSharedMemorySize,
                         FLASH_SMEM);

    // 1) LN1
    ln_kernel<<<MM, 256>>>(x, xn, alpha1, beta1);

    // 2-4) projections: q,k split-tf32; v plain
    {
        dim3 g(DD / 128, MM / 128);
        gemm_nt<1><<<g, 256>>>(xn, wq, bq, nullptr, q, MM, DD, DD, DD, DD, DD, 1, 0, 0);
        gemm_nt<1><<<g, 256>>>(xn, wk, bk, nullptr, k, MM, DD, DD, DD, DD, DD, 1, 0, 0);
        gemm_nt<0><<<g, 256>>>(xn, wv, bv, nullptr, v, MM, DD, DD, DD, DD, DD, 1, 0, 0);
    }

    // 5) fused attention
    {
        dim3 g(SS / 128, BB * HH);
        flash_kernel<<<g, 256, FLASH_SMEM>>>(q, k, v, mask, attn);
    }

    // 6) x1 = x + attn @ wo^T + bo
    {
        dim3 g(DD / 128, MM / 128);
        gemm_nt<0><<<g, 256>>>(attn, wo, bo, x, x1, MM, DD, DD, DD, DD, DD, 1, 0, 1);
    }

    // 7) LN2
    ln_kernel<<<MM, 256>>>(x1, xn, alpha2, beta2);

    // 8) h = relu(xn @ w1^T + b1)
    {
        dim3 g(FF / 128, MM / 128);
        gemm_nt<0><<<g, 256>>>(xn, w1, b1, nullptr, h, MM, FF, DD, DD, DD, FF, 1, 1, 0);
    }

    // 9) out = x1 + h @ w2^T + b2
    {
        dim3 g(DD / 128, MM / 128);
        gemm_nt<0><<<g, 256>>>(h, w2, b2, x1, out, MM, DD, FF, FF, FF, DD, 1, 0, 1);
    }
}

// round 4
// speedup vs baseline: 2.7170x; 1.0970x over previous
#include <cuda_runtime.h>
#include <cuda_bf16.h>
#include <math.h>
#include <stdint.h>

// Problem constants
#define BB 2
#define SS 2048
#define DD 1024
#define FF 4096
#define HH 16
#define DKK 64
#define MM (BB*SS)          // 4096

// ---------------- scratch (static device memory; no allocation APIs) ----------------
__device__ float g_xn   [MM*DD];
__device__ float g_q    [MM*DD];
__device__ float g_k    [MM*DD];
__device__ float g_v    [MM*DD];
__device__ float g_attn [MM*DD];
__device__ float g_x1   [MM*DD];
__device__ float g_h    [MM*FF];

// ---------------- reductions ----------------
__device__ __forceinline__ float warpSum(float v) {
#pragma unroll
    for (int o = 16; o > 0; o >>= 1) v += __shfl_xor_sync(0xffffffffu, v, o);
    return v;
}
__device__ float blockSum(float v) {
    __shared__ float sh[8];
    int lane = threadIdx.x & 31, w = threadIdx.x >> 5;
    v = warpSum(v);
    if (lane == 0) sh[w] = v;
    __syncthreads();
    if (w == 0) {
        float t = (lane < 8) ? sh[lane] : 0.0f;
        t = warpSum(t);
        if (lane == 0) sh[0] = t;
    }
    __syncthreads();
    float out = sh[0];
    __syncthreads();
    return out;
}

// ---------------- LayerNorm (torch-style: unbiased std, eps added to std) ----------------
__global__ void ln_kernel(const float* __restrict__ x, float* __restrict__ y,
                          const float* __restrict__ alpha, const float* __restrict__ beta) {
    long long row = blockIdx.x;
    const float* xr = x + row * DD;
    float* yr = y + row * DD;
    float v[4];
    float s = 0.0f;
#pragma unroll
    for (int r = 0; r < 4; r++) {
        v[r] = xr[threadIdx.x + r * 256];
        s += v[r];
    }
    float mean = blockSum(s) * (1.0f / DD);
    float s2 = 0.0f;
#pragma unroll
    for (int r = 0; r < 4; r++) {
        float d = v[r] - mean;
        s2 += d * d;
    }
    float var = blockSum(s2) * (1.0f / (DD - 1));
    float a = alpha[0], b = beta[0];
    float inv = a / (sqrtf(var) + 1e-6f);
#pragma unroll
    for (int r = 0; r < 4; r++)
        yr[threadIdx.x + r * 256] = (v[r] - mean) * inv + b;
}

// ---------------- tf32 helpers ----------------
__device__ __forceinline__ uint32_t f2tf(float f) {
    uint32_t r;
    asm("cvt.rna.tf32.f32 %0, %1;" : "=r"(r) : "f"(f));
    return r;
}
__device__ __forceinline__ void mma_tf32(float* c,
                                         uint32_t a0, uint32_t a1, uint32_t a2, uint32_t a3,
                                         uint32_t b0, uint32_t b1) {
    asm volatile(
        "mma.sync.aligned.m16n8k8.row.col.f32.tf32.tf32.f32 "
        "{%0,%1,%2,%3},{%4,%5,%6,%7},{%8,%9},{%0,%1,%2,%3};"
        : "+f"(c[0]), "+f"(c[1]), "+f"(c[2]), "+f"(c[3])
        : "r"(a0), "r"(a1), "r"(a2), "r"(a3), "r"(b0), "r"(b1));
}
__device__ __forceinline__ void cvt_hi(const float4& v, uint4& hi) {
    hi.x = f2tf(v.x); hi.y = f2tf(v.y); hi.z = f2tf(v.z); hi.w = f2tf(v.w);
}
__device__ __forceinline__ void cvt_lo(const float4& v, const uint4& hi, uint4& lo) {
    lo.x = f2tf(v.x - __uint_as_float(hi.x));
    lo.y = f2tf(v.y - __uint_as_float(hi.y));
    lo.z = f2tf(v.z - __uint_as_float(hi.z));
    lo.w = f2tf(v.w - __uint_as_float(hi.w));
}

// ---------------- dense NT GEMM, software-pipelined, tf32 staged in smem ----------------
// C[m,n] = sum_k A[m,k] * B[n,k] (+bias, relu, residual). M%128==0, N%128==0, K%32==0.
// SPLIT=1: hi/lo split-tf32 (fp32-quality), 3 mma per step.
// Double-buffered smem stages + register prefetch; one __syncthreads per K-step.
#define G_AST 20
#define G_TILE (128 * G_AST)

template<int SPLIT>
__global__ void __launch_bounds__(256, 2)
gemm_nt(const float* __restrict__ A, const float* __restrict__ Bm,
        const float* __restrict__ bias, const float* __restrict__ res,
        float* __restrict__ C,
        int M, int N, int K, int lda, int ldb, int ldc,
        int doBias, int doRelu, int doRes)
{
    constexpr int BK = 16;
    extern __shared__ uint32_t dsm[];
    uint32_t* Ah = dsm;                       // 2 stages x G_TILE
    uint32_t* Bh = Ah + 2 * G_TILE;
    uint32_t* Al = SPLIT ? Bh + 2 * G_TILE : Bh;
    uint32_t* Bl = SPLIT ? Al + 2 * G_TILE : Bh;

    const int m0 = blockIdx.y * 128;
    const int n0 = blockIdx.x * 128;
    const int t = threadIdx.x;
    const int lane = t & 31, w = t >> 5;
    const int gid = lane >> 2, tig = lane & 3;
    const int wn = w & 3, wm = w >> 2;          // 4 warps n, 2 warps m
    const int mBase = wm * 64;
    const int nBase = wn * 32;

    // per-thread staging coords (2 chunks of 256 threads cover 128x16 floats)
    int srow[2], skq[2];
#pragma unroll
    for (int it = 0; it < 2; it++) {
        int s = t + it * 256;
        srow[it] = s >> 2;
        skq[it]  = (s & 3) * 4;
    }

    float acc[4][4][4];
#pragma unroll
    for (int i = 0; i < 4; i++)
#pragma unroll
        for (int j = 0; j < 4; j++)
#pragma unroll
            for (int r = 0; r < 4; r++) acc[i][j][r] = 0.0f;

    float4 ra[2], rb[2];
    // prologue: load tile 0 into regs
#pragma unroll
    for (int it = 0; it < 2; it++) {
        ra[it] = *(const float4*)(A + (long long)(m0 + srow[it]) * lda + skq[it]);
        rb[it] = *(const float4*)(Bm + (long long)(n0 + srow[it]) * ldb + skq[it]);
    }
    // stage tile 0 into buffer 0
#pragma unroll
    for (int it = 0; it < 2; it++) {
        int off = srow[it] * G_AST + skq[it];
        uint4 hi, lo;
        cvt_hi(ra[it], hi); *(uint4*)&Ah[off] = hi;
        if (SPLIT) { cvt_lo(ra[it], hi, lo); *(uint4*)&Al[off] = lo; }
        cvt_hi(rb[it], hi); *(uint4*)&Bh[off] = hi;
        if (SPLIT) { cvt_lo(rb[it], hi, lo); *(uint4*)&Bl[off] = lo; }
    }
    __syncthreads();

    int buf = 0;
    for (int k0 = 0; k0 < K; k0 += BK) {
        const bool notlast = (k0 + BK) < K;
        // issue next tile's global loads early (latency hidden by mma below)
        if (notlast) {
#pragma unroll
            for (int it = 0; it < 2; it++) {
                ra[it] = *(const float4*)(A + (long long)(m0 + srow[it]) * lda + k0 + BK + skq[it]);
                rb[it] = *(const float4*)(Bm + (long long)(n0 + srow[it]) * ldb + k0 + BK + skq[it]);
            }
        }
        // ---- compute on current buffer
        const uint32_t* cAh = Ah + buf * G_TILE;
        const uint32_t* cBh = Bh + buf * G_TILE;
        const uint32_t* cAl = Al + buf * G_TILE;
        const uint32_t* cBl = Bl + buf * G_TILE;
#pragma unroll
        for (int kk = 0; kk < BK; kk += 8) {
            uint32_t bhf[4][2], blf[4][2];
#pragma unroll
            for (int nt = 0; nt < 4; nt++) {
                int nn = nBase + nt * 8 + gid;
                bhf[nt][0] = cBh[nn * G_AST + kk + tig];
                bhf[nt][1] = cBh[nn * G_AST + kk + tig + 4];
                if (SPLIT) {
                    blf[nt][0] = cBl[nn * G_AST + kk + tig];
                    blf[nt][1] = cBl[nn * G_AST + kk + tig + 4];
                }
            }
#pragma unroll
            for (int mt = 0; mt < 4; mt++) {
                int r0 = mBase + mt * 16 + gid;
                uint32_t ah0 = cAh[r0 * G_AST + kk + tig];
                uint32_t ah1 = cAh[(r0 + 8) * G_AST + kk + tig];
                uint32_t ah2 = cAh[r0 * G_AST + kk + tig + 4];
                uint32_t ah3 = cAh[(r0 + 8) * G_AST + kk + tig + 4];
                uint32_t al0, al1, al2, al3;
                if (SPLIT) {
                    al0 = cAl[r0 * G_AST + kk + tig];
                    al1 = cAl[(r0 + 8) * G_AST + kk + tig];
                    al2 = cAl[r0 * G_AST + kk + tig + 4];
                    al3 = cAl[(r0 + 8) * G_AST + kk + tig + 4];
                }
#pragma unroll
                for (int nt = 0; nt < 4; nt++) {
                    mma_tf32(acc[mt][nt], ah0, ah1, ah2, ah3, bhf[nt][0], bhf[nt][1]);
                    if (SPLIT) {
                        mma_tf32(acc[mt][nt], ah0, ah1, ah2, ah3, blf[nt][0], blf[nt][1]);
                        mma_tf32(acc[mt][nt], al0, al1, al2, al3, bhf[nt][0], bhf[nt][1]);
                    }
                }
            }
        }
        // ---- stage next tile into other buffer (no barrier needed before:
        // all warps already past the barrier that released buf^1)
        if (notlast) {
            uint32_t* nAh = Ah + (buf ^ 1) * G_TILE;
            uint32_t* nBh = Bh + (buf ^ 1) * G_TILE;
            uint32_t* nAl = Al + (buf ^ 1) * G_TILE;
            uint32_t* nBl = Bl + (buf ^ 1) * G_TILE;
#pragma unroll
            for (int it = 0; it < 2; it++) {
                int off = srow[it] * G_AST + skq[it];
                uint4 hi, lo;
                cvt_hi(ra[it], hi); *(uint4*)&nAh[off] = hi;
                if (SPLIT) { cvt_lo(ra[it], hi, lo); *(uint4*)&nAl[off] = lo; }
                cvt_hi(rb[it], hi); *(uint4*)&nBh[off] = hi;
                if (SPLIT) { cvt_lo(rb[it], hi, lo); *(uint4*)&nBl[off] = lo; }
            }
            __syncthreads();
            buf ^= 1;
        }
    }

    // ---- epilogue
#pragma unroll
    for (int mt = 0; mt < 4; mt++) {
#pragma unroll
        for (int nt = 0; nt < 4; nt++) {
            int row = m0 + mBase + mt * 16 + gid;
            int col = n0 + nBase + nt * 8 + tig * 2;
            float b0 = 0.f, b1 = 0.f;
            if (doBias) { b0 = bias[col]; b1 = bias[col + 1]; }
#pragma unroll
            for (int half = 0; half < 2; half++) {
                int r = row + half * 8;
                float v0 = acc[mt][nt][half * 2 + 0] + b0;
                float v1 = acc[mt][nt][half * 2 + 1] + b1;
                if (doRelu) { v0 = fmaxf(v0, 0.f); v1 = fmaxf(v1, 0.f); }
                if (doRes) {
                    float2 rr = *(const float2*)(res + (long long)r * ldc + col);
                    v0 += rr.x; v1 += rr.y;
                }
                *(float2*)(C + (long long)r * ldc + col) = make_float2(v0, v1);
            }
        }
    }
}

#define GEMM_SMEM_S0 (2 * 2 * G_TILE * 4)
#define GEMM_SMEM_S1 (4 * 2 * G_TILE * 4)

// ---------------- flash attention ----------------
// Grid (S/128, B*H). 256 threads = 8 warps; warp w owns q-rows [w*16, w*16+16).
// Per key-block of 128: QK^T (split-tf32), masked online softmax, P@V (tf32).
#define KSTR 68
#define VSTR 72
#define PSTR 140
#define FLASH_SMEM (4 * (2 * 128 * KSTR + 128 * VSTR + 128 * PSTR) + 512)

__global__ void __launch_bounds__(256, 1)
flash_kernel(const float* __restrict__ Q, const float* __restrict__ K,
             const float* __restrict__ V, const int* __restrict__ mask,
             float* __restrict__ O)
{
    extern __shared__ char smem_raw[];
    uint32_t* Khi = (uint32_t*)smem_raw;
    uint32_t* Klo = Khi + 128 * KSTR;
    uint32_t* Vs  = Klo + 128 * KSTR;
    uint32_t* Ps  = Vs + 128 * VSTR;
    float*    Qs  = (float*)Ps;                 // reused before first P store
    int*      Ms  = (int*)(Ps + 128 * PSTR);

    const int bh = blockIdx.y;
    const int b = bh >> 4, h = bh & 15;
    const int q0 = blockIdx.x * 128;
    const int t = threadIdx.x, lane = t & 31, w = t >> 5;
    const int gid = lane >> 2, tig = lane & 3;

    const float* Qbase = Q + ((long long)(b * SS + q0)) * DD + h * DKK;
    const float* Kbase = K + ((long long)b * SS) * DD + h * DKK;
    const float* Vbase = V + ((long long)b * SS) * DD + h * DKK;

    // ---- stage Q (fp32) then build per-warp register fragments (hi/lo)
    for (int i = t; i < 2048; i += 256) {
        int r = i >> 4, c = (i & 15) * 4;
        float4 vq = *(const float4*)(Qbase + (long long)r * DD + c);
        *(float4*)&Qs[r * KSTR + c] = vq;
    }
    __syncthreads();

    uint32_t qhi[8][4], qlo[8][4];
    {
        int r0 = w * 16 + gid;
#pragma unroll
        for (int ks = 0; ks < 8; ks++) {
            int c0 = ks * 8 + tig;
            float f0 = Qs[r0 * KSTR + c0];
            float f1 = Qs[(r0 + 8) * KSTR + c0];
            float f2 = Qs[r0 * KSTR + c0 + 4];
            float f3 = Qs[(r0 + 8) * KSTR + c0 + 4];
            qhi[ks][0] = f2tf(f0); qlo[ks][0] = f2tf(f0 - __uint_as_float(qhi[ks][0]));
            qhi[ks][1] = f2tf(f1); qlo[ks][1] = f2tf(f1 - __uint_as_float(qhi[ks][1]));
            qhi[ks][2] = f2tf(f2); qlo[ks][2] = f2tf(f2 - __uint_as_float(qhi[ks][2]));
            qhi[ks][3] = f2tf(f3); qlo[ks][3] = f2tf(f3 - __uint_as_float(qhi[ks][3]));
        }
    }

    float acc[8][4];
#pragma unroll
    for (int i = 0; i < 8; i++)
#pragma unroll
        for (int r = 0; r < 4; r++) acc[i][r] = 0.0f;
    float mrow0 = -1e30f, mrow1 = -1e30f;
    float lrow0 = 0.0f, lrow1 = 0.0f;

    for (int k0 = 0; k0 < SS; k0 += 128) {
        __syncthreads();   // prior iter's reads of Khi/Vs done
        // ---- stage K (hi/lo tf32) and V (tf32)
        for (int i = t; i < 2048; i += 256) {
            int r = i >> 4, c = (i & 15) * 4;
            float4 kv = *(const float4*)(Kbase + (long long)(k0 + r) * DD + c);
            uint4 hi, lo;
            hi.x = f2tf(kv.x); lo.x = f2tf(kv.x - __uint_as_float(hi.x));
            hi.y = f2tf(kv.y); lo.y = f2tf(kv.y - __uint_as_float(hi.y));
            hi.z = f2tf(kv.z); lo.z = f2tf(kv.z - __uint_as_float(hi.z));
            hi.w = f2tf(kv.w); lo.w = f2tf(kv.w - __uint_as_float(hi.w));
            *(uint4*)&Khi[r * KSTR + c] = hi;
            *(uint4*)&Klo[r * KSTR + c] = lo;
            float4 vv = *(const float4*)(Vbase + (long long)(k0 + r) * DD + c);
            uint4 vt;
            vt.x = f2tf(vv.x); vt.y = f2tf(vv.y); vt.z = f2tf(vv.z); vt.w = f2tf(vv.w);
            *(uint4*)&Vs[r * VSTR + c] = vt;
        }
        if (t < 128) Ms[t] = mask[(long long)b * SS + k0 + t];
        __syncthreads();

        // ---- QK^T: s[16][4] covers 16 q-rows x 128 keys for this warp
        float s[16][4];
#pragma unroll
        for (int nt = 0; nt < 16; nt++) {
            s[nt][0] = 0.f; s[nt][1] = 0.f; s[nt][2] = 0.f; s[nt][3] = 0.f;
        }
#pragma unroll
        for (int nt = 0; nt < 16; nt++) {
            int nrow = (nt * 8 + gid) * KSTR;
#pragma unroll
            for (int ks = 0; ks < 8; ks++) {
                int a = nrow + ks * 8 + tig;
                uint32_t kh0 = Khi[a], kh1 = Khi[a + 4];
                uint32_t kl0 = Klo[a], kl1 = Klo[a + 4];
                mma_tf32(s[nt], qhi[ks][0], qhi[ks][1], qhi[ks][2], qhi[ks][3], kh0, kh1);
                mma_tf32(s[nt], qhi[ks][0], qhi[ks][1], qhi[ks][2], qhi[ks][3], kl0, kl1);
                mma_tf32(s[nt], qlo[ks][0], qlo[ks][1], qlo[ks][2], qlo[ks][3], kh0, kh1);
            }
        }

        // ---- mask
#pragma unroll
        for (int nt = 0; nt < 16; nt++) {
            int c = nt * 8 + 2 * tig;
            if (Ms[c] == 0)     { s[nt][0] = -1e30f; s[nt][2] = -1e30f; }
            if (Ms[c + 1] == 0) { s[nt][1] = -1e30f; s[nt][3] = -1e30f; }
        }

        // ---- online softmax (rows gid and gid+8 of warp band)
        float tm0 = -1e30f, tm1 = -1e30f;
#pragma unroll
        for (int nt = 0; nt < 16; nt++) {
            tm0 = fmaxf(tm0, fmaxf(s[nt][0], s[nt][1]));
            tm1 = fmaxf(tm1, fmaxf(s[nt][2], s[nt][3]));
        }
        tm0 = fmaxf(tm0, __shfl_xor_sync(0xffffffffu, tm0, 1));
        tm0 = fmaxf(tm0, __shfl_xor_sync(0xffffffffu, tm0, 2));
        tm1 = fmaxf(tm1, __shfl_xor_sync(0xffffffffu, tm1, 1));
        tm1 = fmaxf(tm1, __shfl_xor_sync(0xffffffffu, tm1, 2));
        float mn0 = fmaxf(mrow0, tm0), mn1 = fmaxf(mrow1, tm1);
        float sc0 = __expf(mrow0 - mn0), sc1 = __expf(mrow1 - mn1);
        mrow0 = mn0; mrow1 = mn1;
        float rs0 = 0.f, rs1 = 0.f;
#pragma unroll
        for (int nt = 0; nt < 16; nt++) {
            s[nt][0] = __expf(s[nt][0] - mn0);
            s[nt][1] = __expf(s[nt][1] - mn0);
            s[nt][2] = __expf(s[nt][2] - mn1);
            s[nt][3] = __expf(s[nt][3] - mn1);
            rs0 += s[nt][0] + s[nt][1];
            rs1 += s[nt][2] + s[nt][3];
        }
        rs0 += __shfl_xor_sync(0xffffffffu, rs0, 1);
        rs0 += __shfl_xor_sync(0xffffffffu, rs0, 2);
        rs1 += __shfl_xor_sync(0xffffffffu, rs1, 1);
        rs1 += __shfl_xor_sync(0xffffffffu, rs1, 2);
        lrow0 = lrow0 * sc0 + rs0;
        lrow1 = lrow1 * sc1 + rs1;
#pragma unroll
        for (int nt = 0; nt < 8; nt++) {
            acc[nt][0] *= sc0; acc[nt][1] *= sc0;
            acc[nt][2] *= sc1; acc[nt][3] *= sc1;
        }

        // ---- store P (tf32) to warp-private rows of Ps
        {
            int r0 = (w * 16 + gid) * PSTR;
            int r1 = (w * 16 + gid + 8) * PSTR;
#pragma unroll
            for (int nt = 0; nt < 16; nt++) {
                int c = nt * 8 + 2 * tig;
                uint2 p0, p1;
                p0.x = f2tf(s[nt][0]); p0.y = f2tf(s[nt][1]);
                p1.x = f2tf(s[nt][2]); p1.y = f2tf(s[nt][3]);
                *(uint2*)&Ps[r0 + c] = p0;
                *(uint2*)&Ps[r1 + c] = p1;
            }
        }
        __syncwarp();

        // ---- P @ V -> acc
        {
            int pr0 = (w * 16 + gid) * PSTR;
            int pr1 = (w * 16 + gid + 8) * PSTR;
#pragma unroll
            for (int ks = 0; ks < 16; ks++) {
                int kk = ks * 8;
                uint32_t a0 = Ps[pr0 + kk + tig];
                uint32_t a1 = Ps[pr1 + kk + tig];
                uint32_t a2 = Ps[pr0 + kk + tig + 4];
                uint32_t a3 = Ps[pr1 + kk + tig + 4];
#pragma unroll
                for (int nt = 0; nt < 8; nt++) {
                    uint32_t b0 = Vs[(kk + tig) * VSTR + nt * 8 + gid];
                    uint32_t b1 = Vs[(kk + tig + 4) * VSTR + nt * 8 + gid];
                    mma_tf32(acc[nt], a0, a1, a2, a3, b0, b1);
                }
            }
        }
    }

    // ---- epilogue: normalize and write O[(b*S + q), h*64 + c]
    float inv0 = 1.0f / lrow0, inv1 = 1.0f / lrow1;
    long long rowg = (long long)(b * SS + q0 + w * 16 + gid);
#pragma unroll
    for (int nt = 0; nt < 8; nt++) {
        int col = h * DKK + nt * 8 + 2 * tig;
        *(float2*)(O + rowg * DD + col) =
            make_float2(acc[nt][0] * inv0, acc[nt][1] * inv0);
        *(float2*)(O + (rowg + 8) * DD + col) =
            make_float2(acc[nt][2] * inv1, acc[nt][3] * inv1);
    }
}

// ---------------- host launch ----------------
extern "C" void kernel_launch(void* const* d_in, const int* in_sizes, int n_in,
                              void* d_out, int out_size) {
    const float* x      = (const float*)d_in[0];
    const int*   mask   = (const int*)  d_in[1];
    const float* wq     = (const float*)d_in[2];
    const float* bq     = (const float*)d_in[3];
    const float* wk     = (const float*)d_in[4];
    const float* bk     = (const float*)d_in[5];
    const float* wv     = (const float*)d_in[6];
    const float* bv     = (const float*)d_in[7];
    const float* wo     = (const float*)d_in[8];
    const float* bo     = (const float*)d_in[9];
    const float* w1     = (const float*)d_in[10];
    const float* b1     = (const float*)d_in[11];
    const float* w2     = (const float*)d_in[12];
    const float* b2     = (const float*)d_in[13];
    const float* alpha1 = (const float*)d_in[14];
    const float* beta1  = (const float*)d_in[15];
    const float* alpha2 = (const float*)d_in[16];
    const float* beta2  = (const float*)d_in[17];
    float* out = (float*)d_out;

    float *xn, *q, *k, *v, *attn, *x1, *h;
    cudaGetSymbolAddress((void**)&xn,   g_xn);
    cudaGetSymbolAddress((void**)&q,    g_q);
    cudaGetSymbolAddress((void**)&k,    g_k);
    cudaGetSymbolAddress((void**)&v,    g_v);
    cudaGetSymbolAddress((void**)&attn, g_attn);
    cudaGetSymbolAddress((void**)&x1,   g_x1);
    cudaGetSymbolAddress((void**)&h,    g_h);

    static int attr_done = 0;
    if (!attr_done) {
        cudaFuncSetAttribute(flash_kernel, cudaFuncAttributeMaxDynamicSharedMemorySize,
                             FLASH_SMEM);
        cudaFuncSetAttribute(gemm_nt<0>, cudaFuncAttributeMaxDynamicSharedMemorySize,
                             GEMM_SMEM_S0);
        cudaFuncSetAttribute(gemm_nt<1>, cudaFuncAttributeMaxDynamicSharedMemorySize,
                             GEMM_SMEM_S1);
        attr_done = 1;
    }

    // 1) LN1
    ln_kernel<<<MM, 256>>>(x, xn, alpha1, beta1);

    // 2-4) projections: q,k split-tf32; v plain
    {
        dim3 g(DD / 128, MM / 128);
        gemm_nt<1><<<g, 256, GEMM_SMEM_S1>>>(xn, wq, bq, nullptr, q, MM, DD, DD, DD, DD, DD, 1, 0, 0);
        gemm_nt<1><<<g, 256, GEMM_SMEM_S1>>>(xn, wk, bk, nullptr, k, MM, DD, DD, DD, DD, DD, 1, 0, 0);
        gemm_nt<0><<<g, 256, GEMM_SMEM_S0>>>(xn, wv, bv, nullptr, v, MM, DD, DD, DD, DD, DD, 1, 0, 0);
    }

    // 5) fused attention
    {
        dim3 g(SS / 128, BB * HH);
        flash_kernel<<<g, 256, FLASH_SMEM>>>(q, k, v, mask, attn);
    }

    // 6) x1 = x + attn @ wo^T + bo
    {
        dim3 g(DD / 128, MM / 128);
        gemm_nt<0><<<g, 256, GEMM_SMEM_S0>>>(attn, wo, bo, x, x1, MM, DD, DD, DD, DD, DD, 1, 0, 1);
    }

    // 7) LN2
    ln_kernel<<<MM, 256>>>(x1, xn, alpha2, beta2);

    // 8) h = relu(xn @ w1^T + b1)
    {
        dim3 g(FF / 128, MM / 128);
        gemm_nt<0><<<g, 256, GEMM_SMEM_S0>>>(xn, w1, b1, nullptr, h, MM, FF, DD, DD, DD, FF, 1, 1, 0);
    }

    // 9) out = x1 + h @ w2^T + b2
    {
        dim3 g(DD / 128, MM / 128);
        gemm_nt<0><<<g, 256, GEMM_SMEM_S0>>>(h, w2, b2, x1, out, MM, DD, FF, FF, FF, DD, 1, 0, 1);
    }
}

// round 5
// speedup vs baseline: 2.8960x; 1.0659x over previous
#include <cuda_runtime.h>
#include <cuda_bf16.h>
#include <math.h>
#include <stdint.h>

// Problem constants
#define BB 2
#define SS 2048
#define DD 1024
#define FF 4096
#define HH 16
#define DKK 64
#define MM (BB*SS)          // 4096

#define WQ0 0
#define WK0 (DD*DD)
#define WV0 (2*DD*DD)
#define WO0 (3*DD*DD)
#define W10 (4*DD*DD)
#define W20 (8*DD*DD)
#define WTOT (12*DD*DD)

// ---------------- scratch (static device memory; no allocation APIs) ----------------
__device__ __align__(256) float g_q   [MM*DD];
__device__ __align__(256) float g_k   [MM*DD];
__device__ __align__(256) float g_v   [MM*DD];
__device__ __align__(256) float g_attn[MM*DD];
__device__ __align__(256) float g_x1  [MM*DD];
__device__ __align__(256) __nv_bfloat16 g_xnh[MM*DD];
__device__ __align__(256) __nv_bfloat16 g_xnl[MM*DD];
__device__ __align__(256) __nv_bfloat16 g_ath[MM*DD];
__device__ __align__(256) __nv_bfloat16 g_atl[MM*DD];
__device__ __align__(256) __nv_bfloat16 g_hh [MM*FF];
__device__ __align__(256) __nv_bfloat16 g_hl [MM*FF];
__device__ __align__(256) __nv_bfloat16 g_wh [WTOT];
__device__ __align__(256) __nv_bfloat16 g_wl [WTOT];

// ---------------- helpers ----------------
__device__ __forceinline__ float warpSum(float v) {
#pragma unroll
    for (int o = 16; o > 0; o >>= 1) v += __shfl_xor_sync(0xffffffffu, v, o);
    return v;
}
__device__ float blockSum(float v) {
    __shared__ float sh[8];
    int lane = threadIdx.x & 31, w = threadIdx.x >> 5;
    v = warpSum(v);
    if (lane == 0) sh[w] = v;
    __syncthreads();
    if (w == 0) {
        float t = (lane < 8) ? sh[lane] : 0.0f;
        t = warpSum(t);
        if (lane == 0) sh[0] = t;
    }
    __syncthreads();
    float out = sh[0];
    __syncthreads();
    return out;
}

__device__ __forceinline__ void bsplit(float f, __nv_bfloat16& h, __nv_bfloat16& l) {
    h = __float2bfloat16_rn(f);
    l = __float2bfloat16_rn(f - __bfloat162float(h));
}

// ---------------- fp32 -> (hi,lo) bf16 split kernel ----------------
__global__ void conv_kernel(const float* __restrict__ s,
                            __nv_bfloat16* __restrict__ ho,
                            __nv_bfloat16* __restrict__ lo, int n4) {
    int i = blockIdx.x * 256 + threadIdx.x;
    if (i >= n4) return;
    float4 v = ((const float4*)s)[i];
    __nv_bfloat16 h0, h1, h2, h3, l0, l1, l2, l3;
    bsplit(v.x, h0, l0); bsplit(v.y, h1, l1);
    bsplit(v.z, h2, l2); bsplit(v.w, h3, l3);
    __nv_bfloat162 p;
    p.x = h0; p.y = h1; ((__nv_bfloat162*)ho)[2 * i] = p;
    p.x = h2; p.y = h3; ((__nv_bfloat162*)ho)[2 * i + 1] = p;
    p.x = l0; p.y = l1; ((__nv_bfloat162*)lo)[2 * i] = p;
    p.x = l2; p.y = l3; ((__nv_bfloat162*)lo)[2 * i + 1] = p;
}

// ---------------- LayerNorm -> hi/lo bf16 ----------------
__global__ void ln_kernel(const float* __restrict__ x,
                          __nv_bfloat16* __restrict__ yh, __nv_bfloat16* __restrict__ yl,
                          const float* __restrict__ alpha, const float* __restrict__ beta) {
    long long row = blockIdx.x;
    const float* xr = x + row * DD;
    float v[4];
    float s = 0.0f;
#pragma unroll
    for (int r = 0; r < 4; r++) {
        v[r] = xr[threadIdx.x + r * 256];
        s += v[r];
    }
    float mean = blockSum(s) * (1.0f / DD);
    float s2 = 0.0f;
#pragma unroll
    for (int r = 0; r < 4; r++) {
        float d = v[r] - mean;
        s2 += d * d;
    }
    float var = blockSum(s2) * (1.0f / (DD - 1));
    float a = alpha[0], b = beta[0];
    float inv = a / (sqrtf(var) + 1e-6f);
#pragma unroll
    for (int r = 0; r < 4; r++) {
        int idx = threadIdx.x + r * 256;
        float o = (v[r] - mean) * inv + b;
        __nv_bfloat16 h, l;
        bsplit(o, h, l);
        yh[row * DD + idx] = h;
        yl[row * DD + idx] = l;
    }
}

// ---------------- mma / ldmatrix / cp.async primitives ----------------
__device__ __forceinline__ uint32_t f2tf(float f) {
    uint32_t r;
    asm("cvt.rna.tf32.f32 %0, %1;" : "=r"(r) : "f"(f));
    return r;
}
__device__ __forceinline__ void mma_tf32(float* c,
                                         uint32_t a0, uint32_t a1, uint32_t a2, uint32_t a3,
                                         uint32_t b0, uint32_t b1) {
    asm volatile(
        "mma.sync.aligned.m16n8k8.row.col.f32.tf32.tf32.f32 "
        "{%0,%1,%2,%3},{%4,%5,%6,%7},{%8,%9},{%0,%1,%2,%3};"
        : "+f"(c[0]), "+f"(c[1]), "+f"(c[2]), "+f"(c[3])
        : "r"(a0), "r"(a1), "r"(a2), "r"(a3), "r"(b0), "r"(b1));
}
__device__ __forceinline__ void mma_bf16(float* c,
                                         const uint32_t* a, uint32_t b0, uint32_t b1) {
    asm volatile(
        "mma.sync.aligned.m16n8k16.row.col.f32.bf16.bf16.f32 "
        "{%0,%1,%2,%3},{%4,%5,%6,%7},{%8,%9},{%0,%1,%2,%3};"
        : "+f"(c[0]), "+f"(c[1]), "+f"(c[2]), "+f"(c[3])
        : "r"(a[0]), "r"(a[1]), "r"(a[2]), "r"(a[3]), "r"(b0), "r"(b1));
}
__device__ __forceinline__ void ldmx4(uint32_t addr, uint32_t& r0, uint32_t& r1,
                                      uint32_t& r2, uint32_t& r3) {
    asm volatile("ldmatrix.sync.aligned.m8n8.x4.shared.b16 {%0,%1,%2,%3}, [%4];"
                 : "=r"(r0), "=r"(r1), "=r"(r2), "=r"(r3) : "r"(addr));
}
__device__ __forceinline__ void cp16(uint32_t d, const void* s) {
    asm volatile("cp.async.cg.shared.global [%0], [%1], 16;" :: "r"(d), "l"(s));
}
__device__ __forceinline__ void cpcommit() { asm volatile("cp.async.commit_group;"); }
template<int N> __device__ __forceinline__ void cpwait() {
    asm volatile("cp.async.wait_group %0;" :: "n"(N));
}

// ---------------- split-bf16 NT GEMM ----------------
// C[m,n] = sum_k A[m,k]*B[n,k], A/B given as (hi,lo) bf16 pairs; 3-mma split
// accumulation in fp32 (~fp32 quality). BM=BN=128, BK=32, 2-stage cp.async.
#define BKD 32
#define STRD 40                         // smem row stride (bf16 elems), 80B: ldmatrix conflict-free
#define TILE_E (128*STRD)               // elems per array per stage
#define GEMM_SMEM (2*4*TILE_E*2)        // bytes = 81920

__global__ void __launch_bounds__(256, 2)
gemm_bf(const __nv_bfloat16* __restrict__ Ah, const __nv_bfloat16* __restrict__ Al,
        const __nv_bfloat16* __restrict__ Bh, const __nv_bfloat16* __restrict__ Bl,
        const float* __restrict__ bias, const float* __restrict__ res,
        float* __restrict__ C, __nv_bfloat16* __restrict__ Ch, __nv_bfloat16* __restrict__ Cl,
        int M, int N, int K,
        int doBias, int doRelu, int doRes, int outBf)
{
    extern __shared__ __nv_bfloat16 sm[];
    const uint32_t sbase = (uint32_t)__cvta_generic_to_shared(sm);

    const int m0 = blockIdx.y * 128, n0 = blockIdx.x * 128;
    const int t = threadIdx.x, lane = t & 31, w = t >> 5;
    const int gid = lane >> 2, tig = lane & 3;
    const int wm = w >> 2, wn = w & 3;
    const int mBase = wm * 64, nBase = wn * 32;
    const int lr = lane & 7, lj = lane >> 3;

    float acc[4][4][4];
#pragma unroll
    for (int i = 0; i < 4; i++)
#pragma unroll
        for (int j = 0; j < 4; j++)
#pragma unroll
            for (int r = 0; r < 4; r++) acc[i][j][r] = 0.0f;

    const __nv_bfloat16* gsrc[4] = {Ah, Al, Bh, Bl};

    auto issue = [&](int kt, int s) {
        int k0 = kt * BKD;
#pragma unroll
        for (int arr = 0; arr < 4; arr++) {
            int rb = (arr < 2) ? m0 : n0;
            const __nv_bfloat16* src = gsrc[arr];
            uint32_t dst = sbase + (uint32_t)(s * 4 + arr) * (TILE_E * 2);
#pragma unroll
            for (int i = 0; i < 2; i++) {
                int c = t + i * 256;
                int row = c >> 2, col = (c & 3) * 8;
                cp16(dst + (uint32_t)(row * STRD + col) * 2,
                     src + (long long)(rb + row) * K + k0 + col);
            }
        }
    };

    const int KT = K / BKD;
    issue(0, 0); cpcommit();
    cpwait<0>();
    __syncthreads();

    int buf = 0;
    for (int kt = 0; kt < KT; kt++) {
        if (kt + 1 < KT) { issue(kt + 1, buf ^ 1); cpcommit(); }

        uint32_t uAh = sbase + (uint32_t)(buf * 4 + 0) * (TILE_E * 2);
        uint32_t uAl = sbase + (uint32_t)(buf * 4 + 1) * (TILE_E * 2);
        uint32_t uBh = sbase + (uint32_t)(buf * 4 + 2) * (TILE_E * 2);
        uint32_t uBl = sbase + (uint32_t)(buf * 4 + 3) * (TILE_E * 2);

#pragma unroll
        for (int kk = 0; kk < BKD; kk += 16) {
            uint32_t bh[4][2], bl[4][2];
#pragma unroll
            for (int p = 0; p < 2; p++) {
                uint32_t off = (uint32_t)((nBase + p * 16 + lr + (lj >> 1) * 8) * STRD
                                          + kk + (lj & 1) * 8) * 2;
                ldmx4(uBh + off, bh[2 * p][0], bh[2 * p][1], bh[2 * p + 1][0], bh[2 * p + 1][1]);
                ldmx4(uBl + off, bl[2 * p][0], bl[2 * p][1], bl[2 * p + 1][0], bl[2 * p + 1][1]);
            }
#pragma unroll
            for (int mt = 0; mt < 4; mt++) {
                uint32_t ah[4], al4[4];
                uint32_t aoff = (uint32_t)((mBase + mt * 16 + lr + (lj & 1) * 8) * STRD
                                           + kk + (lj >> 1) * 8) * 2;
                ldmx4(uAh + aoff, ah[0], ah[1], ah[2], ah[3]);
                ldmx4(uAl + aoff, al4[0], al4[1], al4[2], al4[3]);
#pragma unroll
                for (int nt = 0; nt < 4; nt++) {
                    mma_bf16(acc[mt][nt], ah, bh[nt][0], bh[nt][1]);
                    mma_bf16(acc[mt][nt], ah, bl[nt][0], bl[nt][1]);
                    mma_bf16(acc[mt][nt], al4, bh[nt][0], bh[nt][1]);
                }
            }
        }
        if (kt + 1 < KT) cpwait<0>();
        __syncthreads();
        buf ^= 1;
    }

    // ---- epilogue
#pragma unroll
    for (int mt = 0; mt < 4; mt++) {
#pragma unroll
        for (int nt = 0; nt < 4; nt++) {
            int row = m0 + mBase + mt * 16 + gid;
            int col = n0 + nBase + nt * 8 + tig * 2;
            float b0 = 0.f, b1 = 0.f;
            if (doBias) { b0 = bias[col]; b1 = bias[col + 1]; }
#pragma unroll
            for (int half = 0; half < 2; half++) {
                int r = row + half * 8;
                float v0 = acc[mt][nt][half * 2 + 0] + b0;
                float v1 = acc[mt][nt][half * 2 + 1] + b1;
                if (doRelu) { v0 = fmaxf(v0, 0.f); v1 = fmaxf(v1, 0.f); }
                if (doRes) {
                    float2 rr = *(const float2*)(res + (long long)r * N + col);
                    v0 += rr.x; v1 += rr.y;
                }
                if (outBf) {
                    __nv_bfloat16 h0, l0, h1, l1;
                    bsplit(v0, h0, l0); bsplit(v1, h1, l1);
                    __nv_bfloat162 p;
                    p.x = h0; p.y = h1;
                    *(__nv_bfloat162*)(Ch + (long long)r * N + col) = p;
                    p.x = l0; p.y = l1;
                    *(__nv_bfloat162*)(Cl + (long long)r * N + col) = p;
                } else {
                    *(float2*)(C + (long long)r * N + col) = make_float2(v0, v1);
                }
            }
        }
    }
}

// ---------------- flash attention (tf32, unchanged from R4) ----------------
#define KSTR 68
#define VSTR 72
#define PSTR 140
#define FLASH_SMEM (4 * (2 * 128 * KSTR + 128 * VSTR + 128 * PSTR) + 512)

__global__ void __launch_bounds__(256, 1)
flash_kernel(const float* __restrict__ Q, const float* __restrict__ K,
             const float* __restrict__ V, const int* __restrict__ mask,
             float* __restrict__ O)
{
    extern __shared__ char smem_raw[];
    uint32_t* Khi = (uint32_t*)smem_raw;
    uint32_t* Klo = Khi + 128 * KSTR;
    uint32_t* Vs  = Klo + 128 * KSTR;
    uint32_t* Ps  = Vs + 128 * VSTR;
    float*    Qs  = (float*)Ps;
    int*      Ms  = (int*)(Ps + 128 * PSTR);

    const int bh = blockIdx.y;
    const int b = bh >> 4, h = bh & 15;
    const int q0 = blockIdx.x * 128;
    const int t = threadIdx.x, lane = t & 31, w = t >> 5;
    const int gid = lane >> 2, tig = lane & 3;

    const float* Qbase = Q + ((long long)(b * SS + q0)) * DD + h * DKK;
    const float* Kbase = K + ((long long)b * SS) * DD + h * DKK;
    const float* Vbase = V + ((long long)b * SS) * DD + h * DKK;

    for (int i = t; i < 2048; i += 256) {
        int r = i >> 4, c = (i & 15) * 4;
        float4 vq = *(const float4*)(Qbase + (long long)r * DD + c);
        *(float4*)&Qs[r * KSTR + c] = vq;
    }
    __syncthreads();

    uint32_t qhi[8][4], qlo[8][4];
    {
        int r0 = w * 16 + gid;
#pragma unroll
        for (int ks = 0; ks < 8; ks++) {
            int c0 = ks * 8 + tig;
            float f0 = Qs[r0 * KSTR + c0];
            float f1 = Qs[(r0 + 8) * KSTR + c0];
            float f2 = Qs[r0 * KSTR + c0 + 4];
            float f3 = Qs[(r0 + 8) * KSTR + c0 + 4];
            qhi[ks][0] = f2tf(f0); qlo[ks][0] = f2tf(f0 - __uint_as_float(qhi[ks][0]));
            qhi[ks][1] = f2tf(f1); qlo[ks][1] = f2tf(f1 - __uint_as_float(qhi[ks][1]));
            qhi[ks][2] = f2tf(f2); qlo[ks][2] = f2tf(f2 - __uint_as_float(qhi[ks][2]));
            qhi[ks][3] = f2tf(f3); qlo[ks][3] = f2tf(f3 - __uint_as_float(qhi[ks][3]));
        }
    }

    float acc[8][4];
#pragma unroll
    for (int i = 0; i < 8; i++)
#pragma unroll
        for (int r = 0; r < 4; r++) acc[i][r] = 0.0f;
    float mrow0 = -1e30f, mrow1 = -1e30f;
    float lrow0 = 0.0f, lrow1 = 0.0f;

    for (int k0 = 0; k0 < SS; k0 += 128) {
        __syncthreads();
        for (int i = t; i < 2048; i += 256) {
            int r = i >> 4, c = (i & 15) * 4;
            float4 kv = *(const float4*)(Kbase + (long long)(k0 + r) * DD + c);
            uint4 hi, lo;
            hi.x = f2tf(kv.x); lo.x = f2tf(kv.x - __uint_as_float(hi.x));
            hi.y = f2tf(kv.y); lo.y = f2tf(kv.y - __uint_as_float(hi.y));
            hi.z = f2tf(kv.z); lo.z = f2tf(kv.z - __uint_as_float(hi.z));
            hi.w = f2tf(kv.w); lo.w = f2tf(kv.w - __uint_as_float(hi.w));
            *(uint4*)&Khi[r * KSTR + c] = hi;
            *(uint4*)&Klo[r * KSTR + c] = lo;
            float4 vv = *(const float4*)(Vbase + (long long)(k0 + r) * DD + c);
            uint4 vt;
            vt.x = f2tf(vv.x); vt.y = f2tf(vv.y); vt.z = f2tf(vv.z); vt.w = f2tf(vv.w);
            *(uint4*)&Vs[r * VSTR + c] = vt;
        }
        if (t < 128) Ms[t] = mask[(long long)b * SS + k0 + t];
        __syncthreads();

        float s[16][4];
#pragma unroll
        for (int nt = 0; nt < 16; nt++) {
            s[nt][0] = 0.f; s[nt][1] = 0.f; s[nt][2] = 0.f; s[nt][3] = 0.f;
        }
#pragma unroll
        for (int nt = 0; nt < 16; nt++) {
            int nrow = (nt * 8 + gid) * KSTR;
#pragma unroll
            for (int ks = 0; ks < 8; ks++) {
                int a = nrow + ks * 8 + tig;
                uint32_t kh0 = Khi[a], kh1 = Khi[a + 4];
                uint32_t kl0 = Klo[a], kl1 = Klo[a + 4];
                mma_tf32(s[nt], qhi[ks][0], qhi[ks][1], qhi[ks][2], qhi[ks][3], kh0, kh1);
                mma_tf32(s[nt], qhi[ks][0], qhi[ks][1], qhi[ks][2], qhi[ks][3], kl0, kl1);
                mma_tf32(s[nt], qlo[ks][0], qlo[ks][1], qlo[ks][2], qlo[ks][3], kh0, kh1);
            }
        }

#pragma unroll
        for (int nt = 0; nt < 16; nt++) {
            int c = nt * 8 + 2 * tig;
            if (Ms[c] == 0)     { s[nt][0] = -1e30f; s[nt][2] = -1e30f; }
            if (Ms[c + 1] == 0) { s[nt][1] = -1e30f; s[nt][3] = -1e30f; }
        }

        float tm0 = -1e30f, tm1 = -1e30f;
#pragma unroll
        for (int nt = 0; nt < 16; nt++) {
            tm0 = fmaxf(tm0, fmaxf(s[nt][0], s[nt][1]));
            tm1 = fmaxf(tm1, fmaxf(s[nt][2], s[nt][3]));
        }
        tm0 = fmaxf(tm0, __shfl_xor_sync(0xffffffffu, tm0, 1));
        tm0 = fmaxf(tm0, __shfl_xor_sync(0xffffffffu, tm0, 2));
        tm1 = fmaxf(tm1, __shfl_xor_sync(0xffffffffu, tm1, 1));
        tm1 = fmaxf(tm1, __shfl_xor_sync(0xffffffffu, tm1, 2));
        float mn0 = fmaxf(mrow0, tm0), mn1 = fmaxf(mrow1, tm1);
        float sc0 = __expf(mrow0 - mn0), sc1 = __expf(mrow1 - mn1);
        mrow0 = mn0; mrow1 = mn1;
        float rs0 = 0.f, rs1 = 0.f;
#pragma unroll
        for (int nt = 0; nt < 16; nt++) {
            s[nt][0] = __expf(s[nt][0] - mn0);
            s[nt][1] = __expf(s[nt][1] - mn0);
            s[nt][2] = __expf(s[nt][2] - mn1);
            s[nt][3] = __expf(s[nt][3] - mn1);
            rs0 += s[nt][0] + s[nt][1];
            rs1 += s[nt][2] + s[nt][3];
        }
        rs0 += __shfl_xor_sync(0xffffffffu, rs0, 1);
        rs0 += __shfl_xor_sync(0xffffffffu, rs0, 2);
        rs1 += __shfl_xor_sync(0xffffffffu, rs1, 1);
        rs1 += __shfl_xor_sync(0xffffffffu, rs1, 2);
        lrow0 = lrow0 * sc0 + rs0;
        lrow1 = lrow1 * sc1 + rs1;
#pragma unroll
        for (int nt = 0; nt < 8; nt++) {
            acc[nt][0] *= sc0; acc[nt][1] *= sc0;
            acc[nt][2] *= sc1; acc[nt][3] *= sc1;
        }

        {
            int r0 = (w * 16 + gid) * PSTR;
            int r1 = (w * 16 + gid + 8) * PSTR;
#pragma unroll
            for (int nt = 0; nt < 16; nt++) {
                int c = nt * 8 + 2 * tig;
                uint2 p0, p1;
                p0.x = f2tf(s[nt][0]); p0.y = f2tf(s[nt][1]);
                p1.x = f2tf(s[nt][2]); p1.y = f2tf(s[nt][3]);
                *(uint2*)&Ps[r0 + c] = p0;
                *(uint2*)&Ps[r1 + c] = p1;
            }
        }
        __syncwarp();

        {
            int pr0 = (w * 16 + gid) * PSTR;
            int pr1 = (w * 16 + gid + 8) * PSTR;
#pragma unroll
            for (int ks = 0; ks < 16; ks++) {
                int kk = ks * 8;
                uint32_t a0 = Ps[pr0 + kk + tig];
                uint32_t a1 = Ps[pr1 + kk + tig];
                uint32_t a2 = Ps[pr0 + kk + tig + 4];
                uint32_t a3 = Ps[pr1 + kk + tig + 4];
#pragma unroll
                for (int nt = 0; nt < 8; nt++) {
                    uint32_t b0 = Vs[(kk + tig) * VSTR + nt * 8 + gid];
                    uint32_t b1 = Vs[(kk + tig + 4) * VSTR + nt * 8 + gid];
                    mma_tf32(acc[nt], a0, a1, a2, a3, b0, b1);
                }
            }
        }
    }

    float inv0 = 1.0f / lrow0, inv1 = 1.0f / lrow1;
    long long rowg = (long long)(b * SS + q0 + w * 16 + gid);
#pragma unroll
    for (int nt = 0; nt < 8; nt++) {
        int col = h * DKK + nt * 8 + 2 * tig;
        *(float2*)(O + rowg * DD + col) =
            make_float2(acc[nt][0] * inv0, acc[nt][1] * inv0);
        *(float2*)(O + (rowg + 8) * DD + col) =
            make_float2(acc[nt][2] * inv1, acc[nt][3] * inv1);
    }
}

// ---------------- host launch ----------------
extern "C" void kernel_launch(void* const* d_in, const int* in_sizes, int n_in,
                              void* d_out, int out_size) {
    const float* x      = (const float*)d_in[0];
    const int*   mask   = (const int*)  d_in[1];
    const float* wq     = (const float*)d_in[2];
    const float* bq     = (const float*)d_in[3];
    const float* wk     = (const float*)d_in[4];
    const float* bk     = (const float*)d_in[5];
    const float* wv     = (const float*)d_in[6];
    const float* bv     = (const float*)d_in[7];
    const float* wo     = (const float*)d_in[8];
    const float* bo     = (const float*)d_in[9];
    const float* w1     = (const float*)d_in[10];
    const float* b1     = (const float*)d_in[11];
    const float* w2     = (const float*)d_in[12];
    const float* b2     = (const float*)d_in[13];
    const float* alpha1 = (const float*)d_in[14];
    const float* beta1  = (const float*)d_in[15];
    const float* alpha2 = (const float*)d_in[16];
    const float* beta2  = (const float*)d_in[17];
    float* out = (float*)d_out;

    float *q, *k, *v, *attn, *x1;
    __nv_bfloat16 *xnh, *xnl, *ath, *atl, *hh, *hl, *wh, *wl;
    cudaGetSymbolAddress((void**)&q,    g_q);
    cudaGetSymbolAddress((void**)&k,    g_k);
    cudaGetSymbolAddress((void**)&v,    g_v);
    cudaGetSymbolAddress((void**)&attn, g_attn);
    cudaGetSymbolAddress((void**)&x1,   g_x1);
    cudaGetSymbolAddress((void**)&xnh,  g_xnh);
    cudaGetSymbolAddress((void**)&xnl,  g_xnl);
    cudaGetSymbolAddress((void**)&ath,  g_ath);
    cudaGetSymbolAddress((void**)&atl,  g_atl);
    cudaGetSymbolAddress((void**)&hh,   g_hh);
    cudaGetSymbolAddress((void**)&hl,   g_hl);
    cudaGetSymbolAddress((void**)&wh,   g_wh);
    cudaGetSymbolAddress((void**)&wl,   g_wl);

    cudaFuncSetAttribute(flash_kernel, cudaFuncAttributeMaxDynamicSharedMemorySize, FLASH_SMEM);
    cudaFuncSetAttribute(gemm_bf, cudaFuncAttributeMaxDynamicSharedMemorySize, GEMM_SMEM);

    const int n4w = DD * DD / 4;

    // 0) split weights to bf16 hi/lo
    conv_kernel<<<n4w / 256, 256>>>(wq, wh + WQ0, wl + WQ0, n4w);
    conv_kernel<<<n4w / 256, 256>>>(wk, wh + WK0, wl + WK0, n4w);
    conv_kernel<<<n4w / 256, 256>>>(wv, wh + WV0, wl + WV0, n4w);
    conv_kernel<<<n4w / 256, 256>>>(wo, wh + WO0, wl + WO0, n4w);
    conv_kernel<<<4 * n4w / 256, 256>>>(w1, wh + W10, wl + W10, 4 * n4w);
    conv_kernel<<<4 * n4w / 256, 256>>>(w2, wh + W20, wl + W20, 4 * n4w);

    // 1) LN1 -> xn hi/lo
    ln_kernel<<<MM, 256>>>(x, xnh, xnl, alpha1, beta1);

    // 2-4) projections -> fp32 q/k/v
    {
        dim3 g(DD / 128, MM / 128);
        gemm_bf<<<g, 256, GEMM_SMEM>>>(xnh, xnl, wh + WQ0, wl + WQ0, bq, nullptr,
                                       q, nullptr, nullptr, MM, DD, DD, 1, 0, 0, 0);
        gemm_bf<<<g, 256, GEMM_SMEM>>>(xnh, xnl, wh + WK0, wl + WK0, bk, nullptr,
                                       k, nullptr, nullptr, MM, DD, DD, 1, 0, 0, 0);
        gemm_bf<<<g, 256, GEMM_SMEM>>>(xnh, xnl, wh + WV0, wl + WV0, bv, nullptr,
                                       v, nullptr, nullptr, MM, DD, DD, 1, 0, 0, 0);
    }

    // 5) fused attention (tf32)
    {
        dim3 g(SS / 128, BB * HH);
        flash_kernel<<<g, 256, FLASH_SMEM>>>(q, k, v, mask, attn);
    }

    // 6) attn -> hi/lo, then x1 = x + attn @ wo^T + bo
    conv_kernel<<<(MM * DD / 4) / 256, 256>>>(attn, ath, atl, MM * DD / 4);
    {
        dim3 g(DD / 128, MM / 128);
        gemm_bf<<<g, 256, GEMM_SMEM>>>(ath, atl, wh + WO0, wl + WO0, bo, x,
                                       x1, nullptr, nullptr, MM, DD, DD, 1, 0, 1, 0);
    }

    // 7) LN2 -> xn hi/lo
    ln_kernel<<<MM, 256>>>(x1, xnh, xnl, alpha2, beta2);

    // 8) h = relu(xn @ w1^T + b1) -> hi/lo bf16 (fused split epilogue)
    {
        dim3 g(FF / 128, MM / 128);
        gemm_bf<<<g, 256, GEMM_SMEM>>>(xnh, xnl, wh + W10, wl + W10, b1, nullptr,
                                       nullptr, hh, hl, MM, FF, DD, 1, 1, 0, 1);
    }

    // 9) out = x1 + h @ w2^T + b2
    {
        dim3 g(DD / 128, MM / 128);
        gemm_bf<<<g, 256, GEMM_SMEM>>>(hh, hl, wh + W20, wl + W20, b2, x1,
                                       out, nullptr, nullptr, MM, DD, FF, 1, 0, 1, 0);
    }
}

// round 7
// speedup vs baseline: 5.7474x; 1.9846x over previous
#include <cuda_runtime.h>
#include <cuda_fp16.h>
#include <math.h>
#include <stdint.h>

// Problem constants
#define BB 2
#define SS 2048
#define DD 1024
#define FF 4096
#define HH 16
#define DKK 64
#define MM (BB*SS)          // 4096

#define WQ0 0
#define WK0 (DD*DD)
#define WV0 (2*DD*DD)
#define WO0 (3*DD*DD)
#define W10 (4*DD*DD)
#define W20 (8*DD*DD)
#define WTOT (12*DD*DD)

// ---------------- scratch (static device memory; no allocation APIs) ----------------
__device__ __align__(256) float  g_q  [MM*DD];     // fp32 Q for flash (split in-kernel)
__device__ __align__(256) __half g_khh[MM*DD];
__device__ __align__(256) __half g_khl[MM*DD];
__device__ __align__(256) __half g_vh [MM*DD];
__device__ __align__(256) __half g_ath[MM*DD];     // attention output (fp16)
__device__ __align__(256) float  g_x1 [MM*DD];
__device__ __align__(256) __half g_xnh[MM*DD];
__device__ __align__(256) __half g_xnl[MM*DD];
__device__ __align__(256) __half g_hh [MM*FF];
__device__ __align__(256) __half g_wh [WTOT];
__device__ __align__(256) __half g_wl [WTOT];

// ---------------- helpers ----------------
__device__ __forceinline__ float warpSum(float v) {
#pragma unroll
    for (int o = 16; o > 0; o >>= 1) v += __shfl_xor_sync(0xffffffffu, v, o);
    return v;
}
__device__ float blockSum(float v) {
    __shared__ float sh[8];
    int lane = threadIdx.x & 31, w = threadIdx.x >> 5;
    v = warpSum(v);
    if (lane == 0) sh[w] = v;
    __syncthreads();
    if (w == 0) {
        float t = (lane < 8) ? sh[lane] : 0.0f;
        t = warpSum(t);
        if (lane == 0) sh[0] = t;
    }
    __syncthreads();
    float out = sh[0];
    __syncthreads();
    return out;
}
__device__ __forceinline__ void hsplit(float f, __half& h, __half& l) {
    h = __float2half_rn(f);
    l = __float2half_rn(f - __half2float(h));
}

// ---------------- fp32 -> (hi,lo) fp16 split kernel (weights) ----------------
__global__ void conv_kernel(const float* __restrict__ s,
                            __half* __restrict__ ho, __half* __restrict__ lo, int n4) {
    int i = blockIdx.x * 256 + threadIdx.x;
    if (i >= n4) return;
    float4 v = ((const float4*)s)[i];
    __half h0, h1, h2, h3, l0, l1, l2, l3;
    hsplit(v.x, h0, l0); hsplit(v.y, h1, l1);
    hsplit(v.z, h2, l2); hsplit(v.w, h3, l3);
    __half2 p;
    p.x = h0; p.y = h1; ((__half2*)ho)[2 * i] = p;
    p.x = h2; p.y = h3; ((__half2*)ho)[2 * i + 1] = p;
    p.x = l0; p.y = l1; ((__half2*)lo)[2 * i] = p;
    p.x = l2; p.y = l3; ((__half2*)lo)[2 * i + 1] = p;
}

// ---------------- LayerNorm -> hi/lo fp16 ----------------
__global__ void ln_kernel(const float* __restrict__ x,
                          __half* __restrict__ yh, __half* __restrict__ yl,
                          const float* __restrict__ alpha, const float* __restrict__ beta) {
    long long row = blockIdx.x;
    const float* xr = x + row * DD;
    float v[4];
    float s = 0.0f;
#pragma unroll
    for (int r = 0; r < 4; r++) {
        v[r] = xr[threadIdx.x + r * 256];
        s += v[r];
    }
    float mean = blockSum(s) * (1.0f / DD);
    float s2 = 0.0f;
#pragma unroll
    for (int r = 0; r < 4; r++) {
        float d = v[r] - mean;
        s2 += d * d;
    }
    float var = blockSum(s2) * (1.0f / (DD - 1));
    float a = alpha[0], b = beta[0];
    float inv = a / (sqrtf(var) + 1e-6f);
#pragma unroll
    for (int r = 0; r < 4; r++) {
        int idx = threadIdx.x + r * 256;
        float o = (v[r] - mean) * inv + b;
        __half h, l;
        hsplit(o, h, l);
        yh[row * DD + idx] = h;
        yl[row * DD + idx] = l;
    }
}

// ---------------- PTX primitives ----------------
__device__ __forceinline__ void mma_f16(float* c, const uint32_t* a,
                                        uint32_t b0, uint32_t b1) {
    asm volatile(
        "mma.sync.aligned.m16n8k16.row.col.f32.f16.f16.f32 "
        "{%0,%1,%2,%3},{%4,%5,%6,%7},{%8,%9},{%0,%1,%2,%3};"
        : "+f"(c[0]), "+f"(c[1]), "+f"(c[2]), "+f"(c[3])
        : "r"(a[0]), "r"(a[1]), "r"(a[2]), "r"(a[3]), "r"(b0), "r"(b1));
}
__device__ __forceinline__ void ldmx4(uint32_t addr, uint32_t& r0, uint32_t& r1,
                                      uint32_t& r2, uint32_t& r3) {
    asm volatile("ldmatrix.sync.aligned.m8n8.x4.shared.b16 {%0,%1,%2,%3}, [%4];"
                 : "=r"(r0), "=r"(r1), "=r"(r2), "=r"(r3) : "r"(addr));
}
__device__ __forceinline__ void ldmx2t(uint32_t addr, uint32_t& r0, uint32_t& r1) {
    asm volatile("ldmatrix.sync.aligned.m8n8.x2.trans.shared.b16 {%0,%1}, [%2];"
                 : "=r"(r0), "=r"(r1) : "r"(addr));
}
__device__ __forceinline__ void cp16(uint32_t d, const void* s) {
    asm volatile("cp.async.cg.shared.global [%0], [%1], 16;" :: "r"(d), "l"(s));
}
__device__ __forceinline__ void cpcommit() { asm volatile("cp.async.commit_group;"); }
template<int N> __device__ __forceinline__ void cpwait() {
    asm volatile("cp.async.wait_group %0;" :: "n"(N));
}
__device__ __forceinline__ uint32_t s2u(const void* p) {
    uint32_t a;
    asm("{ .reg .u64 t; cvta.to.shared.u64 t, %1; cvt.u32.u64 %0, t; }" : "=r"(a) : "l"(p));
    return a;
}
__device__ __forceinline__ uint32_t packh2(float a, float b) {
    __half2 h = __floats2half2_rn(a, b);
    return *(uint32_t*)&h;
}

// ---------------- fp16 NT GEMM (SPLIT: 3-mma hi/lo split; else plain 1-mma) ----------------
// C[m,n] = sum_k A[m,k]*B[n,k]. BM=BN=128, BK=32, 2-stage cp.async, ldmatrix.
// outMode: 0 = fp32 C (+res opt), 1 = half Ch (hi only, relu opt), 2 = half Ch+Cl.
#define BKD 32
#define STRD 40                          // halves; 80B row stride, ldmatrix conflict-free
#define TILE_E (128*STRD)

template<int SPLIT>
__global__ void __launch_bounds__(256, 2)
gemm_h(const __half* __restrict__ Ah, const __half* __restrict__ Al,
       const __half* __restrict__ Bh, const __half* __restrict__ Bl,
       const float* __restrict__ bias, const float* __restrict__ res,
       float* __restrict__ C, __half* __restrict__ Ch, __half* __restrict__ Cl,
       int M, int N, int K, int doRelu, int doRes, int outMode)
{
    constexpr int NARR = SPLIT ? 4 : 2;
    extern __shared__ __half sm[];
    const uint32_t sbase = s2u(sm);

    const int m0 = blockIdx.y * 128, n0 = blockIdx.x * 128;
    const int t = threadIdx.x, lane = t & 31, w = t >> 5;
    const int gid = lane >> 2, tig = lane & 3;
    const int wm = w >> 2, wn = w & 3;
    const int mBase = wm * 64, nBase = wn * 32;
    const int lr = lane & 7, lj = lane >> 3;

    float acc[4][4][4];
#pragma unroll
    for (int i = 0; i < 4; i++)
#pragma unroll
        for (int j = 0; j < 4; j++)
#pragma unroll
            for (int r = 0; r < 4; r++) acc[i][j][r] = 0.0f;

    const __half* gsrc[NARR];
    if (SPLIT) { gsrc[0] = Ah; gsrc[1] = Al; gsrc[2] = Bh; gsrc[3] = Bl; }
    else       { gsrc[0] = Ah; gsrc[1] = Bh; }

    auto issue = [&](int kt, int s) {
        int k0 = kt * BKD;
#pragma unroll
        for (int arr = 0; arr < NARR; arr++) {
            const int rb = (arr < (SPLIT ? 2 : 1)) ? m0 : n0;
            const __half* src = gsrc[arr];
            uint32_t dst = sbase + (uint32_t)(s * NARR + arr) * (TILE_E * 2);
#pragma unroll
            for (int i = 0; i < 2; i++) {
                int c = t + i * 256;
                int row = c >> 2, col = (c & 3) * 8;
                cp16(dst + (uint32_t)(row * STRD + col) * 2,
                     src + (long long)(rb + row) * K + k0 + col);
            }
        }
    };

    const int KT = K / BKD;
    issue(0, 0); cpcommit();
    cpwait<0>();
    __syncthreads();

    int buf = 0;
    for (int kt = 0; kt < KT; kt++) {
        if (kt + 1 < KT) { issue(kt + 1, buf ^ 1); cpcommit(); }

        const uint32_t uAh = sbase + (uint32_t)(buf * NARR + 0) * (TILE_E * 2);
        const uint32_t uAl = SPLIT ? sbase + (uint32_t)(buf * NARR + 1) * (TILE_E * 2) : 0;
        const uint32_t uBh = sbase + (uint32_t)(buf * NARR + (SPLIT ? 2 : 1)) * (TILE_E * 2);
        const uint32_t uBl = SPLIT ? sbase + (uint32_t)(buf * NARR + 3) * (TILE_E * 2) : 0;

#pragma unroll
        for (int kk = 0; kk < BKD; kk += 16) {
            uint32_t bh[4][2], bl[4][2];
#pragma unroll
            for (int p = 0; p < 2; p++) {
                uint32_t off = (uint32_t)((nBase + p * 16 + lr + (lj >> 1) * 8) * STRD
                                          + kk + (lj & 1) * 8) * 2;
                ldmx4(uBh + off, bh[2 * p][0], bh[2 * p][1], bh[2 * p + 1][0], bh[2 * p + 1][1]);
                if (SPLIT)
                    ldmx4(uBl + off, bl[2 * p][0], bl[2 * p][1], bl[2 * p + 1][0], bl[2 * p + 1][1]);
            }
#pragma unroll
            for (int mt = 0; mt < 4; mt++) {
                uint32_t ah[4], al4[4];
                uint32_t aoff = (uint32_t)((mBase + mt * 16 + lr + (lj & 1) * 8) * STRD
                                           + kk + (lj >> 1) * 8) * 2;
                ldmx4(uAh + aoff, ah[0], ah[1], ah[2], ah[3]);
                if (SPLIT) ldmx4(uAl + aoff, al4[0], al4[1], al4[2], al4[3]);
#pragma unroll
                for (int nt = 0; nt < 4; nt++) {
                    mma_f16(acc[mt][nt], ah, bh[nt][0], bh[nt][1]);
                    if (SPLIT) {
                        mma_f16(acc[mt][nt], ah, bl[nt][0], bl[nt][1]);
                        mma_f16(acc[mt][nt], al4, bh[nt][0], bh[nt][1]);
                    }
                }
            }
        }
        if (kt + 1 < KT) cpwait<0>();
        __syncthreads();
        buf ^= 1;
    }

    // ---- epilogue
#pragma unroll
    for (int mt = 0; mt < 4; mt++) {
#pragma unroll
        for (int nt = 0; nt < 4; nt++) {
            int row = m0 + mBase + mt * 16 + gid;
            int col = n0 + nBase + nt * 8 + tig * 2;
            float b0 = bias[col], b1 = bias[col + 1];
#pragma unroll
            for (int half = 0; half < 2; half++) {
                int r = row + half * 8;
                float v0 = acc[mt][nt][half * 2 + 0] + b0;
                float v1 = acc[mt][nt][half * 2 + 1] + b1;
                if (doRelu) { v0 = fmaxf(v0, 0.f); v1 = fmaxf(v1, 0.f); }
                if (outMode == 0) {
                    if (doRes) {
                        float2 rr = *(const float2*)(res + (long long)r * N + col);
                        v0 += rr.x; v1 += rr.y;
                    }
                    *(float2*)(C + (long long)r * N + col) = make_float2(v0, v1);
                } else if (outMode == 1) {
                    __half2 p = __floats2half2_rn(v0, v1);
                    *(__half2*)(Ch + (long long)r * N + col) = p;
                } else {
                    __half h0, l0, h1, l1;
                    hsplit(v0, h0, l0); hsplit(v1, h1, l1);
                    __half2 p;
                    p.x = h0; p.y = h1;
                    *(__half2*)(Ch + (long long)r * N + col) = p;
                    p.x = l0; p.y = l1;
                    *(__half2*)(Cl + (long long)r * N + col) = p;
                }
            }
        }
    }
}

#define GEMM_SMEM_S1 (2 * 4 * TILE_E * 2)   // 81920
#define GEMM_SMEM_S0 (2 * 2 * TILE_E * 2)   // 40960

// ---------------- flash attention, fp16 ----------------
// Grid (S/128, B*H), 256 thr = 8 warps; warp w owns q-rows [w*16, (w+1)*16).
// K given pre-split (khh/khl fp16), V pre-converted (vh). Q fp32, split in-kernel.
// QK^T: 3-mma split-fp16. PV: plain fp16, A-frags straight from softmax registers.
#define KST 72                      // halves per smem row (144B)
#define FL_BUF (128*KST)            // halves per array per stage
#define QSTR 68
#define FLASH_SMEM (6 * FL_BUF * 2)

__global__ void __launch_bounds__(256, 1)
flash_kernel(const float* __restrict__ Q, const __half* __restrict__ Khh,
             const __half* __restrict__ Khl, const __half* __restrict__ Vh,
             const int* __restrict__ mask, __half* __restrict__ O)
{
    extern __shared__ __half fsm[];
    __shared__ int Ms[128];
    const uint32_t sb = s2u(fsm);

    const int bh = blockIdx.y;
    const int b = bh >> 4, h = bh & 15;
    const int q0 = blockIdx.x * 128;
    const int t = threadIdx.x, lane = t & 31, w = t >> 5;
    const int gid = lane >> 2, tig = lane & 3;

    auto issue = [&](int kb, int buf) {
        const long long rowbase = (long long)b * SS + kb * 128;
        const __half* srcs[3] = { Khh, Khl, Vh };
#pragma unroll
        for (int arr = 0; arr < 3; arr++) {
            const __half* src = srcs[arr];
            uint32_t dst = sb + (uint32_t)(buf * 3 + arr) * (FL_BUF * 2);
#pragma unroll
            for (int i = 0; i < 4; i++) {
                int idx = t + i * 256;
                int row = idx >> 3, pc = idx & 7;
                cp16(dst + (uint32_t)(row * KST + pc * 8) * 2,
                     src + (rowbase + row) * DD + h * DKK + pc * 8);
            }
        }
    };

    // prologue: start key-block 0 loads, then stage+split Q
    issue(0, 0); cpcommit();

    float* Qs = (float*)(fsm + 3 * FL_BUF);     // overlay on buffer 1 (untouched yet)
    {
        const float* Qbase = Q + ((long long)(b * SS + q0)) * DD + h * DKK;
        for (int i = t; i < 2048; i += 256) {
            int r = i >> 4, c = (i & 15) * 4;
            *(float4*)&Qs[r * QSTR + c] = *(const float4*)(Qbase + (long long)r * DD + c);
        }
    }
    __syncthreads();

    uint32_t qh[4][4], ql[4][4];
    {
        int r0 = w * 16 + gid;
#pragma unroll
        for (int ks = 0; ks < 4; ks++) {
            int k0 = ks * 16;
            float f00 = Qs[r0 * QSTR + k0 + 2 * tig],       f01 = Qs[r0 * QSTR + k0 + 2 * tig + 1];
            float f10 = Qs[(r0 + 8) * QSTR + k0 + 2 * tig], f11 = Qs[(r0 + 8) * QSTR + k0 + 2 * tig + 1];
            float f20 = Qs[r0 * QSTR + k0 + 8 + 2 * tig],       f21 = Qs[r0 * QSTR + k0 + 8 + 2 * tig + 1];
            float f30 = Qs[(r0 + 8) * QSTR + k0 + 8 + 2 * tig], f31 = Qs[(r0 + 8) * QSTR + k0 + 8 + 2 * tig + 1];
            __half h0, l0, h1, l1;
            hsplit(f00, h0, l0); hsplit(f01, h1, l1);
            qh[ks][0] = packh2(__half2float(h0), __half2float(h1));
            ql[ks][0] = packh2(__half2float(l0), __half2float(l1));
            hsplit(f10, h0, l0); hsplit(f11, h1, l1);
            qh[ks][1] = packh2(__half2float(h0), __half2float(h1));
            ql[ks][1] = packh2(__half2float(l0), __half2float(l1));
            hsplit(f20, h0, l0); hsplit(f21, h1, l1);
            qh[ks][2] = packh2(__half2float(h0), __half2float(h1));
            ql[ks][2] = packh2(__half2float(l0), __half2float(l1));
            hsplit(f30, h0, l0); hsplit(f31, h1, l1);
            qh[ks][3] = packh2(__half2float(h0), __half2float(h1));
            ql[ks][3] = packh2(__half2float(l0), __half2float(l1));
        }
    }
    __syncthreads();            // Q overlay reads done before buf1 staging begins

    float acc[8][4];
#pragma unroll
    for (int i = 0; i < 8; i++)
#pragma unroll
        for (int r = 0; r < 4; r++) acc[i][r] = 0.0f;
    float mrow0 = -1e30f, mrow1 = -1e30f;
    float lrow0 = 0.0f, lrow1 = 0.0f;

    for (int kb = 0; kb < SS / 128; kb++) {
        const int buf = kb & 1;
        if (kb + 1 < SS / 128) { issue(kb + 1, buf ^ 1); cpcommit(); }
        if (t < 128) Ms[t] = mask[(long long)b * SS + kb * 128 + t];
        if (kb + 1 < SS / 128) cpwait<1>(); else cpwait<0>();
        __syncthreads();

        const uint32_t bKhh = sb + (uint32_t)(buf * 3 + 0) * (FL_BUF * 2);
        const uint32_t bKhl = sb + (uint32_t)(buf * 3 + 1) * (FL_BUF * 2);
        const uint32_t bV   = sb + (uint32_t)(buf * 3 + 2) * (FL_BUF * 2);
        const int lr = lane & 7, lj = lane >> 3;

        // ---- QK^T: 16 key-tiles of 8, 4 k16 steps, 3-term split
        float s[16][4];
#pragma unroll
        for (int nt = 0; nt < 16; nt++) {
            s[nt][0] = 0.f; s[nt][1] = 0.f; s[nt][2] = 0.f; s[nt][3] = 0.f;
        }
#pragma unroll
        for (int ks = 0; ks < 4; ks++) {
#pragma unroll
            for (int pp = 0; pp < 8; pp++) {
                uint32_t off = (uint32_t)((pp * 16 + lr + (lj >> 1) * 8) * KST
                                          + ks * 16 + (lj & 1) * 8) * 2;
                uint32_t r0, r1, r2, r3, e0, e1, e2, e3;
                ldmx4(bKhh + off, r0, r1, r2, r3);
                ldmx4(bKhl + off, e0, e1, e2, e3);
                mma_f16(s[2 * pp],     qh[ks], r0, r1);
                mma_f16(s[2 * pp],     ql[ks], r0, r1);
                mma_f16(s[2 * pp],     qh[ks], e0, e1);
                mma_f16(s[2 * pp + 1], qh[ks], r2, r3);
                mma_f16(s[2 * pp + 1], ql[ks], r2, r3);
                mma_f16(s[2 * pp + 1], qh[ks], e2, e3);
            }
        }

        // ---- mask
#pragma unroll
        for (int nt = 0; nt < 16; nt++) {
            int c = nt * 8 + 2 * tig;
            if (Ms[c] == 0)     { s[nt][0] = -1e30f; s[nt][2] = -1e30f; }
            if (Ms[c + 1] == 0) { s[nt][1] = -1e30f; s[nt][3] = -1e30f; }
        }

        // ---- online softmax (rows gid, gid+8)
        float tm0 = -1e30f, tm1 = -1e30f;
#pragma unroll
        for (int nt = 0; nt < 16; nt++) {
            tm0 = fmaxf(tm0, fmaxf(s[nt][0], s[nt][1]));
            tm1 = fmaxf(tm1, fmaxf(s[nt][2], s[nt][3]));
        }
        tm0 = fmaxf(tm0, __shfl_xor_sync(0xffffffffu, tm0, 1));
        tm0 = fmaxf(tm0, __shfl_xor_sync(0xffffffffu, tm0, 2));
        tm1 = fmaxf(tm1, __shfl_xor_sync(0xffffffffu, tm1, 1));
        tm1 = fmaxf(tm1, __shfl_xor_sync(0xffffffffu, tm1, 2));
        float mn0 = fmaxf(mrow0, tm0), mn1 = fmaxf(mrow1, tm1);
        float sc0 = __expf(mrow0 - mn0), sc1 = __expf(mrow1 - mn1);
        mrow0 = mn0; mrow1 = mn1;
        float rs0 = 0.f, rs1 = 0.f;
#pragma unroll
        for (int nt = 0; nt < 16; nt++) {
            s[nt][0] = __expf(s[nt][0] - mn0);
            s[nt][1] = __expf(s[nt][1] - mn0);
            s[nt][2] = __expf(s[nt][2] - mn1);
            s[nt][3] = __expf(s[nt][3] - mn1);
            rs0 += s[nt][0] + s[nt][1];
            rs1 += s[nt][2] + s[nt][3];
        }
        rs0 += __shfl_xor_sync(0xffffffffu, rs0, 1);
        rs0 += __shfl_xor_sync(0xffffffffu, rs0, 2);
        rs1 += __shfl_xor_sync(0xffffffffu, rs1, 1);
        rs1 += __shfl_xor_sync(0xffffffffu, rs1, 2);
        lrow0 = lrow0 * sc0 + rs0;
        lrow1 = lrow1 * sc1 + rs1;
#pragma unroll
        for (int nt = 0; nt < 8; nt++) {
            acc[nt][0] *= sc0; acc[nt][1] *= sc0;
            acc[nt][2] *= sc1; acc[nt][3] *= sc1;
        }

        // ---- P @ V: A-frags straight from registers, V via ldmatrix.trans
        const int li = lane & 15;
#pragma unroll
        for (int ks = 0; ks < 8; ks++) {
            uint32_t a[4];
            a[0] = packh2(s[2 * ks][0],     s[2 * ks][1]);
            a[1] = packh2(s[2 * ks][2],     s[2 * ks][3]);
            a[2] = packh2(s[2 * ks + 1][0], s[2 * ks + 1][1]);
            a[3] = packh2(s[2 * ks + 1][2], s[2 * ks + 1][3]);
#pragma unroll
            for (int nt2 = 0; nt2 < 8; nt2++) {
                uint32_t off = (uint32_t)((ks * 16 + (li & 7) + (li >> 3) * 8) * KST
                                          + nt2 * 8) * 2;
                uint32_t b0, b1;
                ldmx2t(bV + off, b0, b1);
                mma_f16(acc[nt2], a, b0, b1);
            }
        }
        __syncthreads();        // all warps done with this buffer before re-staging
    }

    // ---- epilogue: normalize, write fp16 attn
    float inv0 = 1.0f / lrow0, inv1 = 1.0f / lrow1;
    long long rowg = (long long)(b * SS + q0 + w * 16 + gid);
#pragma unroll
    for (int nt = 0; nt < 8; nt++) {
        int col = h * DKK + nt * 8 + 2 * tig;
        __half2 p0 = __floats2half2_rn(acc[nt][0] * inv0, acc[nt][1] * inv0);
        __half2 p1 = __floats2half2_rn(acc[nt][2] * inv1, acc[nt][3] * inv1);
        *(__half2*)(O + rowg * DD + col) = p0;
        *(__half2*)(O + (rowg + 8) * DD + col) = p1;
    }
}

// ---------------- host launch ----------------
extern "C" void kernel_launch(void* const* d_in, const int* in_sizes, int n_in,
                              void* d_out, int out_size) {
    const float* x      = (const float*)d_in[0];
    const int*   mask   = (const int*)  d_in[1];
    const float* wq     = (const float*)d_in[2];
    const float* bq     = (const float*)d_in[3];
    const float* wk     = (const float*)d_in[4];
    const float* bk     = (const float*)d_in[5];
    const float* wv     = (const float*)d_in[6];
    const float* bv     = (const float*)d_in[7];
    const float* wo     = (const float*)d_in[8];
    const float* bo     = (const float*)d_in[9];
    const float* w1     = (const float*)d_in[10];
    const float* b1     = (const float*)d_in[11];
    const float* w2     = (const float*)d_in[12];
    const float* b2     = (const float*)d_in[13];
    const float* alpha1 = (const float*)d_in[14];
    const float* beta1  = (const float*)d_in[15];
    const float* alpha2 = (const float*)d_in[16];
    const float* beta2  = (const float*)d_in[17];
    float* out = (float*)d_out;

    float *q, *x1;
    __half *khh, *khl, *vh, *ath, *xnh, *xnl, *hh, *wh, *wl;
    cudaGetSymbolAddress((void**)&q,   g_q);
    cudaGetSymbolAddress((void**)&x1,  g_x1);
    cudaGetSymbolAddress((void**)&khh, g_khh);
    cudaGetSymbolAddress((void**)&khl, g_khl);
    cudaGetSymbolAddress((void**)&vh,  g_vh);
    cudaGetSymbolAddress((void**)&ath, g_ath);
    cudaGetSymbolAddress((void**)&xnh, g_xnh);
    cudaGetSymbolAddress((void**)&xnl, g_xnl);
    cudaGetSymbolAddress((void**)&hh,  g_hh);
    cudaGetSymbolAddress((void**)&wh,  g_wh);
    cudaGetSymbolAddress((void**)&wl,  g_wl);

    cudaFuncSetAttribute(flash_kernel, cudaFuncAttributeMaxDynamicSharedMemorySize, FLASH_SMEM);
    cudaFuncSetAttribute(gemm_h<1>, cudaFuncAttributeMaxDynamicSharedMemorySize, GEMM_SMEM_S1);
    cudaFuncSetAttribute(gemm_h<0>, cudaFuncAttributeMaxDynamicSharedMemorySize, GEMM_SMEM_S0);

    const int n4w = DD * DD / 4;

    // 0) split weights to fp16 hi/lo
    conv_kernel<<<n4w / 256, 256>>>(wq, wh + WQ0, wl + WQ0, n4w);
    conv_kernel<<<n4w / 256, 256>>>(wk, wh + WK0, wl + WK0, n4w);
    conv_kernel<<<n4w / 256, 256>>>(wv, wh + WV0, wl + WV0, n4w);
    conv_kernel<<<n4w / 256, 256>>>(wo, wh + WO0, wl + WO0, n4w);
    conv_kernel<<<4 * n4w / 256, 256>>>(w1, wh + W10, wl + W10, 4 * n4w);
    conv_kernel<<<4 * n4w / 256, 256>>>(w2, wh + W20, wl + W20, 4 * n4w);

    // 1) LN1 -> xn hi/lo
    ln_kernel<<<MM, 256>>>(x, xnh, xnl, alpha1, beta1);

    // 2-4) projections: q (fp32 out, split), k (half hi/lo out, split), v (half, plain)
    {
        dim3 g(DD / 128, MM / 128);
        gemm_h<1><<<g, 256, GEMM_SMEM_S1>>>(xnh, xnl, wh + WQ0, wl + WQ0, bq, nullptr,
                                            q, nullptr, nullptr, MM, DD, DD, 0, 0, 0);
        gemm_h<1><<<g, 256, GEMM_SMEM_S1>>>(xnh, xnl, wh + WK0, wl + WK0, bk, nullptr,
                                            nullptr, khh, khl, MM, DD, DD, 0, 0, 2);
        gemm_h<0><<<g, 256, GEMM_SMEM_S0>>>(xnh, nullptr, wh + WV0, nullptr, bv, nullptr,
                                            nullptr, vh, nullptr, MM, DD, DD, 0, 0, 1);
    }

    // 5) fused attention (fp16) -> ath
    {
        dim3 g(SS / 128, BB * HH);
        flash_kernel<<<g, 256, FLASH_SMEM>>>(q, khh, khl, vh, mask, ath);
    }

    // 6) x1 = x + attn @ wo^T + bo  (plain fp16)
    {
        dim3 g(DD / 128, MM / 128);
        gemm_h<0><<<g, 256, GEMM_SMEM_S0>>>(ath, nullptr, wh + WO0, nullptr, bo, x,
                                            x1, nullptr, nullptr, MM, DD, DD, 0, 1, 0);
    }

    // 7) LN2 -> xn hi/lo
    ln_kernel<<<MM, 256>>>(x1, xnh, xnl, alpha2, beta2);

    // 8) h = relu(xn @ w1^T + b1) -> fp16 (plain)
    {
        dim3 g(FF / 128, MM / 128);
        gemm_h<0><<<g, 256, GEMM_SMEM_S0>>>(xnh, nullptr, wh + W10, nullptr, b1, nullptr,
                                            nullptr, hh, nullptr, MM, FF, DD, 1, 0, 1);
    }

    // 9) out = x1 + h @ w2^T + b2  (plain fp16)
    {
        dim3 g(DD / 128, MM / 128);
        gemm_h<0><<<g, 256, GEMM_SMEM_S0>>>(hh, nullptr, wh + W20, nullptr, b2, x1,
                                            out, nullptr, nullptr, MM, DD, FF, 0, 1, 0);
    }
}